// round 1
// baseline (speedup 1.0000x reference)
#include <cuda_runtime.h>
#include <cstddef>

// Problem constants (fixed shapes).
#define BATCH 2
#define SEQ   2048
#define HID   2048
#define NH    16
#define HD    128
#define QKVN  (3*HID)   // 6144

// Scratch (device globals; no allocations allowed).
__device__ float g_qkv[(size_t)BATCH * SEQ * QKVN];   // [4096][6144]
__device__ float g_ctx[(size_t)BATCH * SEQ * HID];    // [4096][2048]

// ---------------------------------------------------------------------------
// SGEMM: C[M,N] = A[M,K] @ B[K,N] (+ bias). 128x128x16 tile, 8x8/thread, 256t.
// ---------------------------------------------------------------------------
template<bool BIAS>
__device__ __forceinline__ void sgemm_body(
    const float* __restrict__ A, const float* __restrict__ Bm,
    const float* __restrict__ bias, float* __restrict__ C,
    int M, int N, int K)
{
  __shared__ __align__(16) float As[128*20];  // [m][k] pad 20 (16B-aligned rows)
  __shared__ __align__(16) float Bs[16*128];  // [k][n]
  const int tid = threadIdx.x;
  const int tx  = tid & 15;
  const int ty  = tid >> 4;
  const int m0  = blockIdx.y << 7;
  const int n0  = blockIdx.x << 7;

  float acc[8][8];
#pragma unroll
  for (int i = 0; i < 8; ++i)
#pragma unroll
    for (int j = 0; j < 8; ++j) acc[i][j] = 0.f;

  int arow[2], acg[2], brow[2], bcol[2];
#pragma unroll
  for (int i = 0; i < 2; ++i) {
    int lin = tid + i*256;
    arow[i] = lin >> 2;  acg[i]  = (lin & 3) << 2;
    brow[i] = lin >> 5;  bcol[i] = (lin & 31) << 2;
  }

  float4 pa[2], pb[2];
#pragma unroll
  for (int i = 0; i < 2; ++i) {
    pa[i] = *(const float4*)&A [(size_t)(m0 + arow[i])*K + acg[i]];
    pb[i] = *(const float4*)&Bm[(size_t)brow[i]*N + n0 + bcol[i]];
  }
#pragma unroll
  for (int i = 0; i < 2; ++i) {
    *(float4*)&As[arow[i]*20 + acg[i]]      = pa[i];
    *(float4*)&Bs[(brow[i]<<7) + bcol[i]]   = pb[i];
  }
  __syncthreads();

  const int KT = K >> 4;
  for (int kt = 0; kt < KT; ++kt) {
    if (kt + 1 < KT) {                      // prefetch next tile into registers
      const int kb = (kt + 1) << 4;
#pragma unroll
      for (int i = 0; i < 2; ++i) {
        pa[i] = *(const float4*)&A [(size_t)(m0 + arow[i])*K + kb + acg[i]];
        pb[i] = *(const float4*)&Bm[(size_t)(kb + brow[i])*N + n0 + bcol[i]];
      }
    }
#pragma unroll
    for (int kk = 0; kk < 16; ++kk) {
      float a[8];
#pragma unroll
      for (int i = 0; i < 8; ++i) a[i] = As[(ty*8 + i)*20 + kk];  // broadcast
      float4 b0 = *(const float4*)&Bs[(kk<<7) + tx*8];
      float4 b1 = *(const float4*)&Bs[(kk<<7) + tx*8 + 4];
      float bb[8] = {b0.x,b0.y,b0.z,b0.w,b1.x,b1.y,b1.z,b1.w};
#pragma unroll
      for (int i = 0; i < 8; ++i)
#pragma unroll
        for (int j = 0; j < 8; ++j) acc[i][j] = fmaf(a[i], bb[j], acc[i][j]);
    }
    __syncthreads();
    if (kt + 1 < KT) {
#pragma unroll
      for (int i = 0; i < 2; ++i) {
        *(float4*)&As[arow[i]*20 + acg[i]]    = pa[i];
        *(float4*)&Bs[(brow[i]<<7) + bcol[i]] = pb[i];
      }
      __syncthreads();
    }
  }

#pragma unroll
  for (int i = 0; i < 8; ++i) {
    const size_t row = (size_t)(m0 + ty*8 + i);
#pragma unroll
    for (int j0 = 0; j0 < 8; j0 += 4) {
      float4 v;
      v.x = acc[i][j0+0]; v.y = acc[i][j0+1];
      v.z = acc[i][j0+2]; v.w = acc[i][j0+3];
      if (BIAS) {
        const int nb = n0 + tx*8 + j0;
        v.x += bias[nb+0]; v.y += bias[nb+1];
        v.z += bias[nb+2]; v.w += bias[nb+3];
      }
      *(float4*)&C[row*N + n0 + tx*8 + j0] = v;
    }
  }
}

__global__ void __launch_bounds__(256) k_qkv(const float* __restrict__ x,
                                             const float* __restrict__ w,
                                             const float* __restrict__ b)
{
  sgemm_body<true>(x, w, b, g_qkv, BATCH*SEQ, QKVN, HID);
}

__global__ void __launch_bounds__(256) k_out(const float* __restrict__ w,
                                             float* __restrict__ out)
{
  sgemm_body<false>(g_ctx, w, nullptr, out, BATCH*SEQ, HID, HID);
}

// ---------------------------------------------------------------------------
// Flash attention (causal, fp32). Block = (q-tile 64) x (head) x (batch).
// 256 threads: tx = tid&15 owns 4 q-rows (m = tx*4+i); ty = tid>>4.
// S-GEMM:  S[m][j], j = ty*4+jj, reduce over k=hd.
// PV-GEMM: O[m][d], d = ty*8+dd, reduce over j.
// ---------------------------------------------------------------------------
#define ATT_QT_STR  68    // Qt [128][68]  (transposed, [k][m])
#define ATT_KV_STR  132   // Ks/Vs [64][132] (natural, [row][k])
#define ATT_PT_STR  68    // Pt [64][68]   (transposed, [j][m])
#define ATT_RED_STR 68    // red [16][68]

#define ATT_SMEM_FLOATS (128*ATT_QT_STR + 2*64*ATT_KV_STR + 64*ATT_PT_STR + 16*ATT_RED_STR)
#define ATT_SMEM_BYTES  (ATT_SMEM_FLOATS * 4)   // 124160 B

__global__ void __launch_bounds__(256) k_attn()
{
  extern __shared__ __align__(16) float sm[];
  float* Qt  = sm;                         // [128][68]
  float* Ks  = Qt  + 128*ATT_QT_STR;       // [64][132]
  float* Vs  = Ks  + 64*ATT_KV_STR;        // [64][132]
  float* Pt  = Vs  + 64*ATT_KV_STR;        // [64][68]
  float* red = Pt  + 64*ATT_PT_STR;        // [16][68]

  const int tid = threadIdx.x;
  const int tx  = tid & 15;
  const int ty  = tid >> 4;
  const int qt  = (int)gridDim.x - 1 - (int)blockIdx.x;  // heavy tiles first
  const int h   = blockIdx.y;
  const int b   = blockIdx.z;
  const int q0  = qt * 64;
  const float* __restrict__ qkv = g_qkv;

  // Stage Q transposed: Qt[k][m]. Coalesced gmem reads; scattered STS (once).
  for (int lin = tid; lin < 64*32; lin += 256) {
    const int r  = lin >> 5;
    const int c4 = (lin & 31) << 2;
    float4 v = *(const float4*)&qkv[(size_t)(b*SEQ + q0 + r)*QKVN + h*HD + c4];
    Qt[(c4+0)*ATT_QT_STR + r] = v.x;
    Qt[(c4+1)*ATT_QT_STR + r] = v.y;
    Qt[(c4+2)*ATT_QT_STR + r] = v.z;
    Qt[(c4+3)*ATT_QT_STR + r] = v.w;
  }

  float mrow[4], lrow[4], O[4][8];
#pragma unroll
  for (int i = 0; i < 4; ++i) {
    mrow[i] = -1e30f; lrow[i] = 0.f;
#pragma unroll
    for (int d = 0; d < 8; ++d) O[i][d] = 0.f;
  }
  const float sc = 0.08838834764831845f;   // 1/sqrt(128)
  __syncthreads();

  for (int kt = 0; kt <= qt; ++kt) {
    const int k0 = kt * 64;

    // Stage K and V tiles (natural layout, coalesced, conflict-free STS.128).
    for (int lin = tid; lin < 64*32; lin += 256) {
      const int r  = lin >> 5;
      const int c4 = (lin & 31) << 2;
      const size_t base = (size_t)(b*SEQ + k0 + r)*QKVN + h*HD + c4;
      *(float4*)&Ks[r*ATT_KV_STR + c4] = *(const float4*)&qkv[base + HID];
      *(float4*)&Vs[r*ATT_KV_STR + c4] = *(const float4*)&qkv[base + 2*HID];
    }
    __syncthreads();

    // S = Q K^T  (4x4 per thread over 64x64 tile)
    float s[4][4];
#pragma unroll
    for (int i = 0; i < 4; ++i)
#pragma unroll
      for (int jj = 0; jj < 4; ++jj) s[i][jj] = 0.f;

#pragma unroll 2
    for (int k = 0; k < HD; k += 4) {
      float4 kb[4];
#pragma unroll
      for (int jj = 0; jj < 4; ++jj)
        kb[jj] = *(const float4*)&Ks[(ty*4 + jj)*ATT_KV_STR + k];   // broadcast
#pragma unroll
      for (int kk = 0; kk < 4; ++kk) {
        float4 qv = *(const float4*)&Qt[(k + kk)*ATT_QT_STR + tx*4]; // vec, cf.
        const float qa[4] = {qv.x, qv.y, qv.z, qv.w};
#pragma unroll
        for (int jj = 0; jj < 4; ++jj) {
          const float bv = ((const float*)&kb[jj])[kk];
#pragma unroll
          for (int i = 0; i < 4; ++i) s[i][jj] = fmaf(qa[i], bv, s[i][jj]);
        }
      }
    }

    // Scale + causal mask (only needed on the diagonal tile).
#pragma unroll
    for (int i = 0; i < 4; ++i)
#pragma unroll
      for (int jj = 0; jj < 4; ++jj) {
        float v = s[i][jj] * sc;
        if (kt == qt && (k0 + ty*4 + jj) > (q0 + tx*4 + i)) v = -1e30f;
        s[i][jj] = v;
      }

    // Row max: local over jj, then cross-ty via smem.
#pragma unroll
    for (int i = 0; i < 4; ++i) {
      float lm = fmaxf(fmaxf(s[i][0], s[i][1]), fmaxf(s[i][2], s[i][3]));
      red[ty*ATT_RED_STR + tx*4 + i] = lm;
    }
    __syncthreads();

    float mnew[4], alpha[4], lsum[4], p[4][4];
#pragma unroll
    for (int i = 0; i < 4; ++i) {
      float mx = -1e30f;
#pragma unroll
      for (int u = 0; u < 16; ++u)
        mx = fmaxf(mx, red[u*ATT_RED_STR + tx*4 + i]);
      mnew[i]  = fmaxf(mrow[i], mx);
      alpha[i] = __expf(mrow[i] - mnew[i]);
      lsum[i]  = 0.f;
#pragma unroll
      for (int jj = 0; jj < 4; ++jj) {
        const float pv = __expf(s[i][jj] - mnew[i]);
        p[i][jj] = pv;
        lsum[i] += pv;
      }
    }
    __syncthreads();   // everyone done reading row-max buffer

    // Row-sum partials + transposed P tile.
#pragma unroll
    for (int i = 0; i < 4; ++i) red[ty*ATT_RED_STR + tx*4 + i] = lsum[i];
#pragma unroll
    for (int jj = 0; jj < 4; ++jj) {
      float4 pv = make_float4(p[0][jj], p[1][jj], p[2][jj], p[3][jj]);
      *(float4*)&Pt[(ty*4 + jj)*ATT_PT_STR + tx*4] = pv;
    }
    __syncthreads();

#pragma unroll
    for (int i = 0; i < 4; ++i) {
      float ts = 0.f;
#pragma unroll
      for (int u = 0; u < 16; ++u) ts += red[u*ATT_RED_STR + tx*4 + i];
      lrow[i] = lrow[i]*alpha[i] + ts;
      mrow[i] = mnew[i];
#pragma unroll
      for (int d = 0; d < 8; ++d) O[i][d] *= alpha[i];
    }

    // O += P V
#pragma unroll 8
    for (int j = 0; j < 64; ++j) {
      float4 pj = *(const float4*)&Pt[j*ATT_PT_STR + tx*4];   // vec, cf.
      float4 v0 = *(const float4*)&Vs[j*ATT_KV_STR + ty*8];   // broadcast
      float4 v1 = *(const float4*)&Vs[j*ATT_KV_STR + ty*8 + 4];
      const float pr[4] = {pj.x, pj.y, pj.z, pj.w};
      const float vv[8] = {v0.x,v0.y,v0.z,v0.w,v1.x,v1.y,v1.z,v1.w};
#pragma unroll
      for (int i = 0; i < 4; ++i)
#pragma unroll
        for (int d = 0; d < 8; ++d) O[i][d] = fmaf(pr[i], vv[d], O[i][d]);
    }
    __syncthreads();   // before next tile restages Ks/Vs/Pt/red
  }

  // Normalize + write ctx.
#pragma unroll
  for (int i = 0; i < 4; ++i) {
    const float inv = 1.0f / lrow[i];
    const size_t row = (size_t)(b*SEQ + q0 + tx*4 + i);
    float4 o0, o1;
    o0.x = O[i][0]*inv; o0.y = O[i][1]*inv; o0.z = O[i][2]*inv; o0.w = O[i][3]*inv;
    o1.x = O[i][4]*inv; o1.y = O[i][5]*inv; o1.z = O[i][6]*inv; o1.w = O[i][7]*inv;
    *(float4*)&g_ctx[row*HID + h*HD + ty*8    ] = o0;
    *(float4*)&g_ctx[row*HID + h*HD + ty*8 + 4] = o1;
  }
}

// ---------------------------------------------------------------------------
extern "C" void kernel_launch(void* const* d_in, const int* in_sizes, int n_in,
                              void* d_out, int out_size)
{
  const float* x     = (const float*)d_in[0];
  const float* w_qkv = (const float*)d_in[1];
  const float* b_qkv = (const float*)d_in[2];
  const float* w_o   = (const float*)d_in[3];
  float* out = (float*)d_out;

  cudaFuncSetAttribute(k_attn, cudaFuncAttributeMaxDynamicSharedMemorySize,
                       ATT_SMEM_BYTES);

  k_qkv<<<dim3(QKVN/128, (BATCH*SEQ)/128), 256>>>(x, w_qkv, b_qkv);
  k_attn<<<dim3(SEQ/64, NH, BATCH), 256, ATT_SMEM_BYTES>>>();
  k_out<<<dim3(HID/128, (BATCH*SEQ)/128), 256>>>(w_o, out);
}

// round 3
// speedup vs baseline: 1.9334x; 1.9334x over previous
#include <cuda_runtime.h>
#include <cuda_bf16.h>
#include <cstdint>
#include <cstddef>

// Problem constants (fixed shapes).
#define BATCH 2
#define SEQ   2048
#define HID   2048
#define NH    16
#define HD    128
#define QKVN  (3*HID)   // 6144
#define MTOT  (BATCH*SEQ)

// Scratch (device globals; no allocations allowed).
__device__ float g_qkv[(size_t)MTOT * QKVN];
__device__ float g_ctx[(size_t)MTOT * HID];
__device__ __nv_bfloat16 g_ahi[(size_t)MTOT*HID];
__device__ __nv_bfloat16 g_alo[(size_t)MTOT*HID];
__device__ __nv_bfloat16 g_bhi[(size_t)QKVN*HID];   // weights^T [N][2048]
__device__ __nv_bfloat16 g_blo[(size_t)QKVN*HID];

// ===========================================================================
// PTX helpers (sm_80-compatible: cp.async + ldmatrix + mma.sync)
// ===========================================================================
__device__ __forceinline__ unsigned smem_u32(const void* p) {
  unsigned a;
  asm("{ .reg .u64 t; cvta.to.shared.u64 t, %1; cvt.u32.u64 %0, t; }"
      : "=r"(a) : "l"(p));
  return a;
}
__device__ __forceinline__ void cp16(unsigned dst, const void* src) {
  asm volatile("cp.async.cg.shared.global [%0], [%1], 16;"
               :: "r"(dst), "l"(__cvta_generic_to_global(src)));
}
__device__ __forceinline__ void cp_commit() {
  asm volatile("cp.async.commit_group;" ::: "memory");
}
__device__ __forceinline__ void cp_wait2() {
  asm volatile("cp.async.wait_group 2;" ::: "memory");
}
__device__ __forceinline__ void ldsm4(unsigned* r, unsigned addr) {
  asm volatile("ldmatrix.sync.aligned.m8n8.x4.shared.b16 {%0,%1,%2,%3}, [%4];"
               : "=r"(r[0]), "=r"(r[1]), "=r"(r[2]), "=r"(r[3]) : "r"(addr));
}
__device__ __forceinline__ void mma_bf16(float* d, const unsigned* a,
                                         const unsigned* b) {
  asm volatile(
    "mma.sync.aligned.m16n8k16.row.col.f32.bf16.bf16.f32 "
    "{%0,%1,%2,%3}, {%4,%5,%6,%7}, {%8,%9}, {%0,%1,%2,%3};"
    : "+f"(d[0]), "+f"(d[1]), "+f"(d[2]), "+f"(d[3])
    : "r"(a[0]), "r"(a[1]), "r"(a[2]), "r"(a[3]), "r"(b[0]), "r"(b[1]));
}

// ===========================================================================
// fp32 -> bf16 hi/lo split (elementwise). use_ctx selects g_ctx as source.
// ===========================================================================
__global__ void __launch_bounds__(256) k_split(const float4* __restrict__ in,
                                               int n4, int use_ctx)
{
  int i = blockIdx.x * 256 + threadIdx.x;
  if (i >= n4) return;
  const float4* src = use_ctx ? (const float4*)g_ctx : in;
  float4 v = src[i];
  __nv_bfloat16 h0 = __float2bfloat16(v.x), h1 = __float2bfloat16(v.y);
  __nv_bfloat16 h2 = __float2bfloat16(v.z), h3 = __float2bfloat16(v.w);
  __nv_bfloat16 l0 = __float2bfloat16(v.x - __bfloat162float(h0));
  __nv_bfloat16 l1 = __float2bfloat16(v.y - __bfloat162float(h1));
  __nv_bfloat16 l2 = __float2bfloat16(v.z - __bfloat162float(h2));
  __nv_bfloat16 l3 = __float2bfloat16(v.w - __bfloat162float(h3));
  __nv_bfloat162* hi = (__nv_bfloat162*)g_ahi;
  __nv_bfloat162* lo = (__nv_bfloat162*)g_alo;
  hi[2*i]   = __nv_bfloat162(h0, h1);
  hi[2*i+1] = __nv_bfloat162(h2, h3);
  lo[2*i]   = __nv_bfloat162(l0, l1);
  lo[2*i+1] = __nv_bfloat162(l2, l3);
}

// ===========================================================================
// w [K=2048][N] fp32 -> transposed hi/lo bf16 [N][2048] into g_bhi/g_blo
// ===========================================================================
__global__ void __launch_bounds__(256) k_splitT(const float* __restrict__ w,
                                                int N)
{
  __shared__ float t[32][33];
  const int n0 = blockIdx.x * 32, k0 = blockIdx.y * 32;
  const int tx = threadIdx.x & 31, ty = threadIdx.x >> 5;
#pragma unroll
  for (int i = 0; i < 4; ++i)
    t[ty + i*8][tx] = w[(size_t)(k0 + ty + i*8) * N + n0 + tx];
  __syncthreads();
#pragma unroll
  for (int i = 0; i < 4; ++i) {
    const int n = n0 + ty + i*8, k = k0 + tx;
    float v = t[tx][ty + i*8];
    __nv_bfloat16 h = __float2bfloat16(v);
    g_bhi[(size_t)n * HID + k] = h;
    g_blo[(size_t)n * HID + k] = __float2bfloat16(v - __bfloat162float(h));
  }
}

// ===========================================================================
// HMMA bf16 3-term split GEMM: C[M][N] = A[M][2048] @ B^T[N][2048] (+bias)
// CTA 128x128, KC=32, 4-stage cp.async pipeline, 8 warps (4M x 2N),
// warp tile 32x64, mma.sync.m16n8k16.
// Smem stage: Ahi|Alo|Bhi|Blo, each [128][40] bf16 (pad-8 rows, 80B stride).
// ===========================================================================
#define KC 32
#define GST 4
#define MATB 10240u                 // 128*40*2 bytes
#define STAGEB (4u*MATB)            // 40960
#define G_SMEM (GST*STAGEB)         // 163840

template<bool BIAS>
__global__ void __launch_bounds__(256) k_gemm(const float* __restrict__ bias,
                                              float* __restrict__ Carg, int N)
{
  extern __shared__ __align__(128) char smem[];
  const unsigned sbase = smem_u32(smem);
  const int tid  = threadIdx.x;
  const int lane = tid & 31, wid = tid >> 5;
  const int m0 = blockIdx.y * 128, n0 = blockIdx.x * 128;
  float* __restrict__ C = Carg ? Carg : g_qkv;
  const int K = HID;
  const int NC = K / KC;            // 64

  // cp.async chunk map: q in [0,2048): mat(512-chunk groups), row, 16B seg.
  auto load_chunk = [&](int c) {
    const unsigned st = sbase + (unsigned)(c & (GST-1)) * STAGEB;
    const int koff = c * KC;
#pragma unroll
    for (int i = 0; i < 8; ++i) {
      const int q   = tid + i * 256;
      const int mat = q >> 9, idx = q & 511, row = idx >> 2, seg = idx & 3;
      const __nv_bfloat16* base =
        (mat == 0) ? g_ahi : (mat == 1) ? g_alo : (mat == 2) ? g_bhi : g_blo;
      const int grow = ((mat < 2) ? m0 : n0) + row;
      cp16(st + (unsigned)mat * MATB + (unsigned)row * 80u + (unsigned)seg * 16u,
           base + (size_t)grow * K + koff + seg * 8);
    }
  };

  // Warp tiling: wm in [0,4) -> 32 M-rows; wn in [0,2) -> 64 N-cols.
  const int wm = wid & 3, wn = wid >> 2;
  // ldmatrix per-thread base offsets (A and B lane patterns differ).
  const unsigned aoff0 = (unsigned)(wm*32 + (lane & 15)) * 80u
                       + (unsigned)(lane >> 4) * 16u;
  const unsigned boff0 = 2u*MATB
                       + (unsigned)(wn*64 + (lane & 7) + ((lane >> 4) << 3)) * 80u
                       + (unsigned)((lane >> 3) & 1) * 16u;

  float acc[2][8][4];
#pragma unroll
  for (int mi = 0; mi < 2; ++mi)
#pragma unroll
    for (int nt = 0; nt < 8; ++nt)
#pragma unroll
      for (int r = 0; r < 4; ++r) acc[mi][nt][r] = 0.f;

  load_chunk(0); cp_commit();
  load_chunk(1); cp_commit();
  load_chunk(2); cp_commit();

  for (int c = 0; c < NC; ++c) {
    cp_wait2();              // stage c resident
    __syncthreads();         // visible to all; prev-iter reads done
    if (c + 3 < NC) load_chunk(c + 3);
    cp_commit();             // empty group near the tail keeps counts aligned

    const unsigned st = sbase + (unsigned)(c & (GST-1)) * STAGEB;
#pragma unroll
    for (int ks = 0; ks < 2; ++ks) {
      unsigned ah[2][4], al[2][4], bh[4][4], bl[4][4];
#pragma unroll
      for (int mi = 0; mi < 2; ++mi) {
        const unsigned a = st + aoff0 + (unsigned)mi*1280u + (unsigned)ks*32u;
        ldsm4(ah[mi], a);
        ldsm4(al[mi], a + MATB);
      }
#pragma unroll
      for (int nj = 0; nj < 4; ++nj) {
        const unsigned b = st + boff0 + (unsigned)nj*1280u + (unsigned)ks*32u;
        ldsm4(bh[nj], b);
        ldsm4(bl[nj], b + MATB);
      }
#pragma unroll
      for (int mi = 0; mi < 2; ++mi)
#pragma unroll
        for (int nt = 0; nt < 8; ++nt) {
          const unsigned* Bh = &bh[nt >> 1][(nt & 1) * 2];
          const unsigned* Bl = &bl[nt >> 1][(nt & 1) * 2];
          mma_bf16(acc[mi][nt], ah[mi], Bh);   // hi*hi
          mma_bf16(acc[mi][nt], ah[mi], Bl);   // hi*lo
          mma_bf16(acc[mi][nt], al[mi], Bh);   // lo*hi
        }
    }
  }

  // Epilogue: fp32 accumulators -> global (+bias).
  const int mrow  = m0 + wm*32 + lane/4;
  const int nbase = n0 + wn*64;
#pragma unroll
  for (int mi = 0; mi < 2; ++mi)
#pragma unroll
    for (int nt = 0; nt < 8; ++nt) {
      const int n  = nbase + nt*8 + (lane & 3)*2;
      const int r0 = mrow + mi*16;
      float2 v0 = make_float2(acc[mi][nt][0], acc[mi][nt][1]);
      float2 v1 = make_float2(acc[mi][nt][2], acc[mi][nt][3]);
      if (BIAS) {
        const float2 bv = *(const float2*)&bias[n];
        v0.x += bv.x; v0.y += bv.y;
        v1.x += bv.x; v1.y += bv.y;
      }
      *(float2*)&C[(size_t)r0 * N + n]       = v0;
      *(float2*)&C[(size_t)(r0 + 8) * N + n] = v1;
    }
}

// ---------------------------------------------------------------------------
// Flash attention (causal, fp32) — unchanged from R1.
// ---------------------------------------------------------------------------
#define ATT_QT_STR  68
#define ATT_KV_STR  132
#define ATT_PT_STR  68
#define ATT_RED_STR 68
#define ATT_SMEM_FLOATS (128*ATT_QT_STR + 2*64*ATT_KV_STR + 64*ATT_PT_STR + 16*ATT_RED_STR)
#define ATT_SMEM_BYTES  (ATT_SMEM_FLOATS * 4)

__global__ void __launch_bounds__(256) k_attn()
{
  extern __shared__ __align__(16) float sm[];
  float* Qt  = sm;
  float* Ks  = Qt  + 128*ATT_QT_STR;
  float* Vs  = Ks  + 64*ATT_KV_STR;
  float* Pt  = Vs  + 64*ATT_KV_STR;
  float* red = Pt  + 64*ATT_PT_STR;

  const int tid = threadIdx.x;
  const int tx  = tid & 15;
  const int ty  = tid >> 4;
  const int qt  = (int)gridDim.x - 1 - (int)blockIdx.x;
  const int h   = blockIdx.y;
  const int b   = blockIdx.z;
  const int q0  = qt * 64;
  const float* __restrict__ qkv = g_qkv;

  for (int lin = tid; lin < 64*32; lin += 256) {
    const int r  = lin >> 5;
    const int c4 = (lin & 31) << 2;
    float4 v = *(const float4*)&qkv[(size_t)(b*SEQ + q0 + r)*QKVN + h*HD + c4];
    Qt[(c4+0)*ATT_QT_STR + r] = v.x;
    Qt[(c4+1)*ATT_QT_STR + r] = v.y;
    Qt[(c4+2)*ATT_QT_STR + r] = v.z;
    Qt[(c4+3)*ATT_QT_STR + r] = v.w;
  }

  float mrow[4], lrow[4], O[4][8];
#pragma unroll
  for (int i = 0; i < 4; ++i) {
    mrow[i] = -1e30f; lrow[i] = 0.f;
#pragma unroll
    for (int d = 0; d < 8; ++d) O[i][d] = 0.f;
  }
  const float sc = 0.08838834764831845f;
  __syncthreads();

  for (int kt = 0; kt <= qt; ++kt) {
    const int k0 = kt * 64;
    for (int lin = tid; lin < 64*32; lin += 256) {
      const int r  = lin >> 5;
      const int c4 = (lin & 31) << 2;
      const size_t base = (size_t)(b*SEQ + k0 + r)*QKVN + h*HD + c4;
      *(float4*)&Ks[r*ATT_KV_STR + c4] = *(const float4*)&qkv[base + HID];
      *(float4*)&Vs[r*ATT_KV_STR + c4] = *(const float4*)&qkv[base + 2*HID];
    }
    __syncthreads();

    float s[4][4];
#pragma unroll
    for (int i = 0; i < 4; ++i)
#pragma unroll
      for (int jj = 0; jj < 4; ++jj) s[i][jj] = 0.f;

#pragma unroll 2
    for (int k = 0; k < HD; k += 4) {
      float4 kb[4];
#pragma unroll
      for (int jj = 0; jj < 4; ++jj)
        kb[jj] = *(const float4*)&Ks[(ty*4 + jj)*ATT_KV_STR + k];
#pragma unroll
      for (int kk = 0; kk < 4; ++kk) {
        float4 qv = *(const float4*)&Qt[(k + kk)*ATT_QT_STR + tx*4];
        const float qa[4] = {qv.x, qv.y, qv.z, qv.w};
#pragma unroll
        for (int jj = 0; jj < 4; ++jj) {
          const float bv = ((const float*)&kb[jj])[kk];
#pragma unroll
          for (int i = 0; i < 4; ++i) s[i][jj] = fmaf(qa[i], bv, s[i][jj]);
        }
      }
    }

#pragma unroll
    for (int i = 0; i < 4; ++i)
#pragma unroll
      for (int jj = 0; jj < 4; ++jj) {
        float v = s[i][jj] * sc;
        if (kt == qt && (k0 + ty*4 + jj) > (q0 + tx*4 + i)) v = -1e30f;
        s[i][jj] = v;
      }

#pragma unroll
    for (int i = 0; i < 4; ++i) {
      float lm = fmaxf(fmaxf(s[i][0], s[i][1]), fmaxf(s[i][2], s[i][3]));
      red[ty*ATT_RED_STR + tx*4 + i] = lm;
    }
    __syncthreads();

    float mnew[4], alpha[4], lsum[4], p[4][4];
#pragma unroll
    for (int i = 0; i < 4; ++i) {
      float mx = -1e30f;
#pragma unroll
      for (int u = 0; u < 16; ++u)
        mx = fmaxf(mx, red[u*ATT_RED_STR + tx*4 + i]);
      mnew[i]  = fmaxf(mrow[i], mx);
      alpha[i] = __expf(mrow[i] - mnew[i]);
      lsum[i]  = 0.f;
#pragma unroll
      for (int jj = 0; jj < 4; ++jj) {
        const float pv = __expf(s[i][jj] - mnew[i]);
        p[i][jj] = pv;
        lsum[i] += pv;
      }
    }
    __syncthreads();

#pragma unroll
    for (int i = 0; i < 4; ++i) red[ty*ATT_RED_STR + tx*4 + i] = lsum[i];
#pragma unroll
    for (int jj = 0; jj < 4; ++jj) {
      float4 pv = make_float4(p[0][jj], p[1][jj], p[2][jj], p[3][jj]);
      *(float4*)&Pt[(ty*4 + jj)*ATT_PT_STR + tx*4] = pv;
    }
    __syncthreads();

#pragma unroll
    for (int i = 0; i < 4; ++i) {
      float ts = 0.f;
#pragma unroll
      for (int u = 0; u < 16; ++u) ts += red[u*ATT_RED_STR + tx*4 + i];
      lrow[i] = lrow[i]*alpha[i] + ts;
      mrow[i] = mnew[i];
#pragma unroll
      for (int d = 0; d < 8; ++d) O[i][d] *= alpha[i];
    }

#pragma unroll 8
    for (int j = 0; j < 64; ++j) {
      float4 pj = *(const float4*)&Pt[j*ATT_PT_STR + tx*4];
      float4 v0 = *(const float4*)&Vs[j*ATT_KV_STR + ty*8];
      float4 v1 = *(const float4*)&Vs[j*ATT_KV_STR + ty*8 + 4];
      const float pr[4] = {pj.x, pj.y, pj.z, pj.w};
      const float vv[8] = {v0.x,v0.y,v0.z,v0.w,v1.x,v1.y,v1.z,v1.w};
#pragma unroll
      for (int i = 0; i < 4; ++i)
#pragma unroll
        for (int d = 0; d < 8; ++d) O[i][d] = fmaf(pr[i], vv[d], O[i][d]);
    }
    __syncthreads();
  }

#pragma unroll
  for (int i = 0; i < 4; ++i) {
    const float inv = 1.0f / lrow[i];
    const size_t row = (size_t)(b*SEQ + q0 + tx*4 + i);
    float4 o0, o1;
    o0.x = O[i][0]*inv; o0.y = O[i][1]*inv; o0.z = O[i][2]*inv; o0.w = O[i][3]*inv;
    o1.x = O[i][4]*inv; o1.y = O[i][5]*inv; o1.z = O[i][6]*inv; o1.w = O[i][7]*inv;
    *(float4*)&g_ctx[row*HID + h*HD + ty*8    ] = o0;
    *(float4*)&g_ctx[row*HID + h*HD + ty*8 + 4] = o1;
  }
}

// ---------------------------------------------------------------------------
extern "C" void kernel_launch(void* const* d_in, const int* in_sizes, int n_in,
                              void* d_out, int out_size)
{
  const float* x     = (const float*)d_in[0];
  const float* w_qkv = (const float*)d_in[1];
  const float* b_qkv = (const float*)d_in[2];
  const float* w_o   = (const float*)d_in[3];
  float* out = (float*)d_out;

  cudaFuncSetAttribute(k_gemm<true>,  cudaFuncAttributeMaxDynamicSharedMemorySize, G_SMEM);
  cudaFuncSetAttribute(k_gemm<false>, cudaFuncAttributeMaxDynamicSharedMemorySize, G_SMEM);
  cudaFuncSetAttribute(k_attn, cudaFuncAttributeMaxDynamicSharedMemorySize, ATT_SMEM_BYTES);

  const int n4x = MTOT*HID/4;   // 2,097,152

  // 1) split x; transpose+split w_qkv
  k_split<<<(n4x + 255)/256, 256>>>((const float4*)x, n4x, 0);
  k_splitT<<<dim3(QKVN/32, HID/32), 256>>>(w_qkv, QKVN);
  // 2) QKV GEMM (HMMA, 3-term split) -> g_qkv
  k_gemm<true><<<dim3(QKVN/128, MTOT/128), 256, G_SMEM>>>(b_qkv, nullptr, QKVN);
  // 3) attention (fp32) -> g_ctx
  k_attn<<<dim3(SEQ/64, NH, BATCH), 256, ATT_SMEM_BYTES>>>();
  // 4) split ctx; transpose+split w_o
  k_split<<<(n4x + 255)/256, 256>>>(nullptr, n4x, 1);
  k_splitT<<<dim3(HID/32, HID/32), 256>>>(w_o, HID);
  // 5) output projection -> d_out
  k_gemm<false><<<dim3(HID/128, MTOT/128), 256, G_SMEM>>>(nullptr, out, HID);
}

// round 4
// speedup vs baseline: 2.9018x; 1.5009x over previous
#include <cuda_runtime.h>
#include <cuda_bf16.h>
#include <cstdint>
#include <cstddef>

// Problem constants (fixed shapes).
#define BATCH 2
#define SEQ   2048
#define HID   2048
#define NH    16
#define HD    128
#define QKVN  (3*HID)   // 6144
#define MTOT  (BATCH*SEQ)

// Scratch (device globals; no allocations allowed).
__device__ __nv_bfloat16 g_ahi[(size_t)MTOT*HID];        // GEMM A hi (x, later ctx)
__device__ __nv_bfloat16 g_alo[(size_t)MTOT*HID];        // GEMM A lo
__device__ __nv_bfloat16 g_bhi[(size_t)QKVN*HID];        // weights^T hi [N][2048]
__device__ __nv_bfloat16 g_blo[(size_t)QKVN*HID];
__device__ __nv_bfloat16 g_qkvhi[(size_t)3*BATCH*NH*SEQ*HD];  // [which][b][h][s][d]
__device__ __nv_bfloat16 g_qkvlo[(size_t)3*BATCH*NH*SEQ*HD];

// ===========================================================================
// PTX helpers (sm_80-compatible: cp.async + ldmatrix + mma.sync)
// ===========================================================================
__device__ __forceinline__ unsigned smem_u32(const void* p) {
  unsigned a;
  asm("{ .reg .u64 t; cvta.to.shared.u64 t, %1; cvt.u32.u64 %0, t; }"
      : "=r"(a) : "l"(p));
  return a;
}
__device__ __forceinline__ void cp16(unsigned dst, const void* src) {
  asm volatile("cp.async.cg.shared.global [%0], [%1], 16;"
               :: "r"(dst), "l"(__cvta_generic_to_global(src)));
}
__device__ __forceinline__ void cp_commit() {
  asm volatile("cp.async.commit_group;" ::: "memory");
}
__device__ __forceinline__ void cp_wait2() {
  asm volatile("cp.async.wait_group 2;" ::: "memory");
}
__device__ __forceinline__ void cp_wait0() {
  asm volatile("cp.async.wait_group 0;" ::: "memory");
}
__device__ __forceinline__ void ldsm4(unsigned* r, unsigned addr) {
  asm volatile("ldmatrix.sync.aligned.m8n8.x4.shared.b16 {%0,%1,%2,%3}, [%4];"
               : "=r"(r[0]), "=r"(r[1]), "=r"(r[2]), "=r"(r[3]) : "r"(addr));
}
__device__ __forceinline__ void ldsm4t(unsigned* r, unsigned addr) {
  asm volatile("ldmatrix.sync.aligned.m8n8.x4.trans.shared.b16 {%0,%1,%2,%3}, [%4];"
               : "=r"(r[0]), "=r"(r[1]), "=r"(r[2]), "=r"(r[3]) : "r"(addr));
}
__device__ __forceinline__ void mma_bf16(float* d, const unsigned* a,
                                         const unsigned* b) {
  asm volatile(
    "mma.sync.aligned.m16n8k16.row.col.f32.bf16.bf16.f32 "
    "{%0,%1,%2,%3}, {%4,%5,%6,%7}, {%8,%9}, {%0,%1,%2,%3};"
    : "+f"(d[0]), "+f"(d[1]), "+f"(d[2]), "+f"(d[3])
    : "r"(a[0]), "r"(a[1]), "r"(a[2]), "r"(a[3]), "r"(b[0]), "r"(b[1]));
}
// pack (lo, hi) -> bf16x2 (lo in low half), and unpack exact fp32 values
__device__ __forceinline__ unsigned packbf(float lo, float hi) {
  unsigned r;
  asm("cvt.rn.bf16x2.f32 %0, %1, %2;" : "=r"(r) : "f"(hi), "f"(lo));
  return r;
}
__device__ __forceinline__ float blo(unsigned r) { return __int_as_float(r << 16); }
__device__ __forceinline__ float bhif(unsigned r) { return __int_as_float(r & 0xFFFF0000u); }

// ===========================================================================
// fp32 -> bf16 hi/lo split (elementwise) into g_ahi/g_alo
// ===========================================================================
__global__ void __launch_bounds__(256) k_split(const float4* __restrict__ in,
                                               int n4)
{
  int i = blockIdx.x * 256 + threadIdx.x;
  if (i >= n4) return;
  float4 v = in[i];
  __nv_bfloat16 h0 = __float2bfloat16(v.x), h1 = __float2bfloat16(v.y);
  __nv_bfloat16 h2 = __float2bfloat16(v.z), h3 = __float2bfloat16(v.w);
  __nv_bfloat16 l0 = __float2bfloat16(v.x - __bfloat162float(h0));
  __nv_bfloat16 l1 = __float2bfloat16(v.y - __bfloat162float(h1));
  __nv_bfloat16 l2 = __float2bfloat16(v.z - __bfloat162float(h2));
  __nv_bfloat16 l3 = __float2bfloat16(v.w - __bfloat162float(h3));
  __nv_bfloat162* hi = (__nv_bfloat162*)g_ahi;
  __nv_bfloat162* lo = (__nv_bfloat162*)g_alo;
  hi[2*i]   = __nv_bfloat162(h0, h1);
  hi[2*i+1] = __nv_bfloat162(h2, h3);
  lo[2*i]   = __nv_bfloat162(l0, l1);
  lo[2*i+1] = __nv_bfloat162(l2, l3);
}

// ===========================================================================
// w [K=2048][N] fp32 -> transposed hi/lo bf16 [N][2048] into g_bhi/g_blo
// ===========================================================================
__global__ void __launch_bounds__(256) k_splitT(const float* __restrict__ w,
                                                int N)
{
  __shared__ float t[32][33];
  const int n0 = blockIdx.x * 32, k0 = blockIdx.y * 32;
  const int tx = threadIdx.x & 31, ty = threadIdx.x >> 5;
#pragma unroll
  for (int i = 0; i < 4; ++i)
    t[ty + i*8][tx] = w[(size_t)(k0 + ty + i*8) * N + n0 + tx];
  __syncthreads();
#pragma unroll
  for (int i = 0; i < 4; ++i) {
    const int n = n0 + ty + i*8, k = k0 + tx;
    float v = t[tx][ty + i*8];
    __nv_bfloat16 h = __float2bfloat16(v);
    g_bhi[(size_t)n * HID + k] = h;
    g_blo[(size_t)n * HID + k] = __float2bfloat16(v - __bfloat162float(h));
  }
}

// ===========================================================================
// HMMA bf16 3-term split GEMM: C[M][N] = A[M][2048] @ B^T[N][2048]
// QKV=true: += bias, then hi/lo split to g_qkvhi/lo in [which][b][h][s][d].
// QKV=false: plain fp32 store to Carg.
// ===========================================================================
#define KC 32
#define GST 4
#define MATB 10240u                 // 128*40*2 bytes
#define STAGEB (4u*MATB)            // 40960
#define G_SMEM (GST*STAGEB)         // 163840

template<bool QKV>
__global__ void __launch_bounds__(256) k_gemm(const float* __restrict__ bias,
                                              float* __restrict__ Carg, int N)
{
  extern __shared__ __align__(128) char smem[];
  const unsigned sbase = smem_u32(smem);
  const int tid  = threadIdx.x;
  const int lane = tid & 31, wid = tid >> 5;
  const int m0 = blockIdx.y * 128, n0 = blockIdx.x * 128;
  const int K = HID;
  const int NC = K / KC;            // 64

  auto load_chunk = [&](int c) {
    const unsigned st = sbase + (unsigned)(c & (GST-1)) * STAGEB;
    const int koff = c * KC;
#pragma unroll
    for (int i = 0; i < 8; ++i) {
      const int q   = tid + i * 256;
      const int mat = q >> 9, idx = q & 511, row = idx >> 2, seg = idx & 3;
      const __nv_bfloat16* base =
        (mat == 0) ? g_ahi : (mat == 1) ? g_alo : (mat == 2) ? g_bhi : g_blo;
      const int grow = ((mat < 2) ? m0 : n0) + row;
      cp16(st + (unsigned)mat * MATB + (unsigned)row * 80u + (unsigned)seg * 16u,
           base + (size_t)grow * K + koff + seg * 8);
    }
  };

  const int wm = wid & 3, wn = wid >> 2;
  const unsigned aoff0 = (unsigned)(wm*32 + (lane & 15)) * 80u
                       + (unsigned)(lane >> 4) * 16u;
  const unsigned boff0 = 2u*MATB
                       + (unsigned)(wn*64 + (lane & 7) + ((lane >> 4) << 3)) * 80u
                       + (unsigned)((lane >> 3) & 1) * 16u;

  float acc[2][8][4];
#pragma unroll
  for (int mi = 0; mi < 2; ++mi)
#pragma unroll
    for (int nt = 0; nt < 8; ++nt)
#pragma unroll
      for (int r = 0; r < 4; ++r) acc[mi][nt][r] = 0.f;

  load_chunk(0); cp_commit();
  load_chunk(1); cp_commit();
  load_chunk(2); cp_commit();

  for (int c = 0; c < NC; ++c) {
    cp_wait2();
    __syncthreads();
    if (c + 3 < NC) load_chunk(c + 3);
    cp_commit();

    const unsigned st = sbase + (unsigned)(c & (GST-1)) * STAGEB;
#pragma unroll
    for (int ks = 0; ks < 2; ++ks) {
      unsigned ah[2][4], al[2][4], bh[4][4], bl[4][4];
#pragma unroll
      for (int mi = 0; mi < 2; ++mi) {
        const unsigned a = st + aoff0 + (unsigned)mi*1280u + (unsigned)ks*32u;
        ldsm4(ah[mi], a);
        ldsm4(al[mi], a + MATB);
      }
#pragma unroll
      for (int nj = 0; nj < 4; ++nj) {
        const unsigned b = st + boff0 + (unsigned)nj*1280u + (unsigned)ks*32u;
        ldsm4(bh[nj], b);
        ldsm4(bl[nj], b + MATB);
      }
#pragma unroll
      for (int mi = 0; mi < 2; ++mi)
#pragma unroll
        for (int nt = 0; nt < 8; ++nt) {
          const unsigned* Bh = &bh[nt >> 1][(nt & 1) * 2];
          const unsigned* Bl = &bl[nt >> 1][(nt & 1) * 2];
          mma_bf16(acc[mi][nt], ah[mi], Bh);
          mma_bf16(acc[mi][nt], ah[mi], Bl);
          mma_bf16(acc[mi][nt], al[mi], Bh);
        }
    }
  }

  const int mrow  = m0 + wm*32 + lane/4;
  const int nbase = n0 + wn*64;
#pragma unroll
  for (int mi = 0; mi < 2; ++mi)
#pragma unroll
    for (int nt = 0; nt < 8; ++nt) {
      const int n  = nbase + nt*8 + (lane & 3)*2;
      const int r0 = mrow + mi*16;
      if (QKV) {
        const float2 bv = *(const float2*)&bias[n];
        const float p0 = acc[mi][nt][0] + bv.x, p1 = acc[mi][nt][1] + bv.y;
        const float p2 = acc[mi][nt][2] + bv.x, p3 = acc[mi][nt][3] + bv.y;
        const int which = n >> 11, hh = (n >> 7) & 15, dd = n & 127;
        const int bb = r0 >> 11, s = r0 & 2047;
        const size_t o0 = ((size_t)((which*BATCH + bb)*NH + hh) * SEQ + s) * HD + dd;
        const size_t o1 = o0 + 8*HD;
        const unsigned h0 = packbf(p0, p1);
        const unsigned l0 = packbf(p0 - blo(h0), p1 - bhif(h0));
        const unsigned h1 = packbf(p2, p3);
        const unsigned l1 = packbf(p2 - blo(h1), p3 - bhif(h1));
        *(unsigned*)&g_qkvhi[o0] = h0;  *(unsigned*)&g_qkvlo[o0] = l0;
        *(unsigned*)&g_qkvhi[o1] = h1;  *(unsigned*)&g_qkvlo[o1] = l1;
      } else {
        float2 v0 = make_float2(acc[mi][nt][0], acc[mi][nt][1]);
        float2 v1 = make_float2(acc[mi][nt][2], acc[mi][nt][3]);
        *(float2*)&Carg[(size_t)r0 * N + n]       = v0;
        *(float2*)&Carg[(size_t)(r0 + 8) * N + n] = v1;
      }
    }
}

// ===========================================================================
// HMMA flash attention (causal). 128 threads (4 warps), q-tile 64, k-tile 64.
// Warp w owns q rows [q0+16w, q0+16w+16). Register softmax via quad shuffles.
// S = qh*kh + qh*kl + ql*kh; PV = ph*vh + ph*vl + pl*vh (all m16n8k16 bf16).
// Smem: Qh|Ql|Kh|Kl|Vh|Vl, each 64 rows x 136 bf16 (272B stride, cf ldmatrix).
// ===========================================================================
#define AT_STR  272u                 // bytes per row
#define AT_MATB 17408u               // 64*272
#define AT_SMEM (6u*AT_MATB)         // 104448

__global__ void __launch_bounds__(128, 2) k_attn()
{
  extern __shared__ __align__(128) char smem[];
  const unsigned sb = smem_u32(smem);
  const int tid = threadIdx.x, lane = tid & 31, w = tid >> 5;
  const int qt = (int)gridDim.x - 1 - (int)blockIdx.x;   // heavy tiles first
  const int h = blockIdx.y, b = blockIdx.z;
  const int q0 = qt * 64;

  const size_t offQ = ((size_t)((0*BATCH + b)*NH + h)) * SEQ * HD;
  const size_t offK = ((size_t)((1*BATCH + b)*NH + h)) * SEQ * HD;
  const size_t offV = ((size_t)((2*BATCH + b)*NH + h)) * SEQ * HD;

  // Stage Q (hi+lo): 2048 16B segs.
#pragma unroll
  for (int i = 0; i < 16; ++i) {
    const int q = tid + i * 128;
    const int mat = q >> 10, row = (q >> 4) & 63, seg = q & 15;
    const __nv_bfloat16* src = (mat ? g_qkvlo : g_qkvhi)
                             + offQ + (size_t)(q0 + row) * HD + seg * 8;
    cp16(sb + (unsigned)mat * AT_MATB + (unsigned)row * AT_STR + (unsigned)seg * 16u, src);
  }

  auto stage_kv = [&](int kt) {
    const int k0 = kt * 64;
#pragma unroll
    for (int i = 0; i < 32; ++i) {
      const int q = tid + i * 128;
      const int mat = q >> 10, row = (q >> 4) & 63, seg = q & 15;
      const __nv_bfloat16* base =
        (mat == 0) ? (g_qkvhi + offK) : (mat == 1) ? (g_qkvlo + offK)
      : (mat == 2) ? (g_qkvhi + offV) : (g_qkvlo + offV);
      cp16(sb + (unsigned)(2 + mat) * AT_MATB + (unsigned)row * AT_STR + (unsigned)seg * 16u,
           base + (size_t)(k0 + row) * HD + seg * 8);
    }
  };

  stage_kv(0);
  cp_commit();

  // ldmatrix per-lane offsets
  const unsigned aoff = (unsigned)(w*16 + (lane & 15)) * AT_STR
                      + (unsigned)(lane >> 4) * 16u;                 // Q (A, row-major)
  const unsigned boff = (unsigned)((lane & 7) + ((lane >> 4) << 3)) * AT_STR
                      + (unsigned)((lane >> 3) & 1) * 16u;           // K (B, col-major)
  const unsigned voff = (unsigned)(lane & 15) * AT_STR
                      + (unsigned)(lane >> 4) * 16u;                 // V (B via trans)

  const float sc = 0.08838834764831845f;   // 1/sqrt(128)
  float m0r = -1e30f, m1r = -1e30f, l0 = 0.f, l1 = 0.f;
  float O[16][4];
#pragma unroll
  for (int nb = 0; nb < 16; ++nb)
#pragma unroll
    for (int r = 0; r < 4; ++r) O[nb][r] = 0.f;

  for (int kt = 0; kt <= qt; ++kt) {
    cp_wait0();
    __syncthreads();

    // ---- S = Q K^T (3-term split), 16x64 per warp ----
    float S[8][4];
#pragma unroll
    for (int nb = 0; nb < 8; ++nb)
#pragma unroll
      for (int r = 0; r < 4; ++r) S[nb][r] = 0.f;

#pragma unroll
    for (int kc = 0; kc < 8; ++kc) {
      unsigned qh[4], ql[4];
      ldsm4(qh, sb + 0*AT_MATB + aoff + (unsigned)kc*32u);
      ldsm4(ql, sb + 1*AT_MATB + aoff + (unsigned)kc*32u);
#pragma unroll
      for (int j = 0; j < 4; ++j) {
        unsigned kh[4], kl[4];
        const unsigned bo = boff + (unsigned)j*4352u + (unsigned)kc*32u;
        ldsm4(kh, sb + 2*AT_MATB + bo);
        ldsm4(kl, sb + 3*AT_MATB + bo);
        mma_bf16(S[2*j],   qh, &kh[0]);  mma_bf16(S[2*j+1], qh, &kh[2]);
        mma_bf16(S[2*j],   qh, &kl[0]);  mma_bf16(S[2*j+1], qh, &kl[2]);
        mma_bf16(S[2*j],   ql, &kh[0]);  mma_bf16(S[2*j+1], ql, &kh[2]);
      }
    }

    // ---- causal mask on diagonal tile ----
    if (kt == qt) {
      const int rl0 = w*16 + (lane >> 2), rl1 = rl0 + 8;
#pragma unroll
      for (int nb = 0; nb < 8; ++nb) {
        const int c0 = nb*8 + 2*(lane & 3), c1 = c0 + 1;
        if (c0 > rl0) S[nb][0] = -1e30f;
        if (c1 > rl0) S[nb][1] = -1e30f;
        if (c0 > rl1) S[nb][2] = -1e30f;
        if (c1 > rl1) S[nb][3] = -1e30f;
      }
    }

    // ---- online softmax (raw-score max; scale folded into exp) ----
    float mx0 = -1e30f, mx1 = -1e30f;
#pragma unroll
    for (int nb = 0; nb < 8; ++nb) {
      mx0 = fmaxf(mx0, fmaxf(S[nb][0], S[nb][1]));
      mx1 = fmaxf(mx1, fmaxf(S[nb][2], S[nb][3]));
    }
    mx0 = fmaxf(mx0, __shfl_xor_sync(0xFFFFFFFFu, mx0, 1));
    mx0 = fmaxf(mx0, __shfl_xor_sync(0xFFFFFFFFu, mx0, 2));
    mx1 = fmaxf(mx1, __shfl_xor_sync(0xFFFFFFFFu, mx1, 1));
    mx1 = fmaxf(mx1, __shfl_xor_sync(0xFFFFFFFFu, mx1, 2));
    const float mn0 = fmaxf(m0r, mx0), mn1 = fmaxf(m1r, mx1);
    const float a0 = __expf(sc * (m0r - mn0));
    const float a1 = __expf(sc * (m1r - mn1));
    m0r = mn0; m1r = mn1;

    float ls0 = 0.f, ls1 = 0.f;
#pragma unroll
    for (int nb = 0; nb < 8; ++nb) {
      S[nb][0] = __expf(sc * (S[nb][0] - mn0));
      S[nb][1] = __expf(sc * (S[nb][1] - mn0));
      S[nb][2] = __expf(sc * (S[nb][2] - mn1));
      S[nb][3] = __expf(sc * (S[nb][3] - mn1));
      ls0 += S[nb][0] + S[nb][1];
      ls1 += S[nb][2] + S[nb][3];
    }
    l0 = l0 * a0 + ls0;
    l1 = l1 * a1 + ls1;

#pragma unroll
    for (int nb = 0; nb < 16; ++nb) {
      O[nb][0] *= a0; O[nb][1] *= a0;
      O[nb][2] *= a1; O[nb][3] *= a1;
    }

    // ---- P hi/lo fragments (A operand for PV) ----
    unsigned ph[4][4], pl[4][4];
#pragma unroll
    for (int kc2 = 0; kc2 < 4; ++kc2) {
      const float* p0 = S[2*kc2];
      const float* p1 = S[2*kc2+1];
      ph[kc2][0] = packbf(p0[0], p0[1]);
      ph[kc2][1] = packbf(p0[2], p0[3]);
      ph[kc2][2] = packbf(p1[0], p1[1]);
      ph[kc2][3] = packbf(p1[2], p1[3]);
      pl[kc2][0] = packbf(p0[0] - blo(ph[kc2][0]), p0[1] - bhif(ph[kc2][0]));
      pl[kc2][1] = packbf(p0[2] - blo(ph[kc2][1]), p0[3] - bhif(ph[kc2][1]));
      pl[kc2][2] = packbf(p1[0] - blo(ph[kc2][2]), p1[1] - bhif(ph[kc2][2]));
      pl[kc2][3] = packbf(p1[2] - blo(ph[kc2][3]), p1[3] - bhif(ph[kc2][3]));
    }

    // ---- O += P V (3-term split), 16x128 per warp ----
#pragma unroll
    for (int kc2 = 0; kc2 < 4; ++kc2) {
#pragma unroll
      for (int j = 0; j < 8; ++j) {
        unsigned vh[4], vl[4];
        const unsigned vo = voff + (unsigned)kc2*4352u + (unsigned)j*32u;
        ldsm4t(vh, sb + 4*AT_MATB + vo);
        ldsm4t(vl, sb + 5*AT_MATB + vo);
        mma_bf16(O[2*j],   ph[kc2], &vh[0]);  mma_bf16(O[2*j+1], ph[kc2], &vh[2]);
        mma_bf16(O[2*j],   ph[kc2], &vl[0]);  mma_bf16(O[2*j+1], ph[kc2], &vl[2]);
        mma_bf16(O[2*j],   pl[kc2], &vh[0]);  mma_bf16(O[2*j+1], pl[kc2], &vh[2]);
      }
    }

    __syncthreads();   // everyone done reading K/V before restage
    if (kt < qt) { stage_kv(kt + 1); }
    cp_commit();
  }

  // ---- finalize: row sums, normalize, write ctx split into g_ahi/g_alo ----
  l0 += __shfl_xor_sync(0xFFFFFFFFu, l0, 1);
  l0 += __shfl_xor_sync(0xFFFFFFFFu, l0, 2);
  l1 += __shfl_xor_sync(0xFFFFFFFFu, l1, 1);
  l1 += __shfl_xor_sync(0xFFFFFFFFu, l1, 2);
  const float inv0 = 1.f / l0, inv1 = 1.f / l1;

  const int s0 = q0 + w*16 + (lane >> 2), s1 = s0 + 8;
  const size_t rb0 = ((size_t)b*SEQ + s0) * HID + h*HD;
  const size_t rb1 = ((size_t)b*SEQ + s1) * HID + h*HD;
#pragma unroll
  for (int nb = 0; nb < 16; ++nb) {
    const int c = nb*8 + 2*(lane & 3);
    const float v0 = O[nb][0]*inv0, v1 = O[nb][1]*inv0;
    const float v2 = O[nb][2]*inv1, v3 = O[nb][3]*inv1;
    const unsigned h0 = packbf(v0, v1);
    const unsigned lo0 = packbf(v0 - blo(h0), v1 - bhif(h0));
    const unsigned h1 = packbf(v2, v3);
    const unsigned lo1 = packbf(v2 - blo(h1), v3 - bhif(h1));
    *(unsigned*)&g_ahi[rb0 + c] = h0;  *(unsigned*)&g_alo[rb0 + c] = lo0;
    *(unsigned*)&g_ahi[rb1 + c] = h1;  *(unsigned*)&g_alo[rb1 + c] = lo1;
  }
}

// ---------------------------------------------------------------------------
extern "C" void kernel_launch(void* const* d_in, const int* in_sizes, int n_in,
                              void* d_out, int out_size)
{
  const float* x     = (const float*)d_in[0];
  const float* w_qkv = (const float*)d_in[1];
  const float* b_qkv = (const float*)d_in[2];
  const float* w_o   = (const float*)d_in[3];
  float* out = (float*)d_out;

  cudaFuncSetAttribute(k_gemm<true>,  cudaFuncAttributeMaxDynamicSharedMemorySize, G_SMEM);
  cudaFuncSetAttribute(k_gemm<false>, cudaFuncAttributeMaxDynamicSharedMemorySize, G_SMEM);
  cudaFuncSetAttribute(k_attn, cudaFuncAttributeMaxDynamicSharedMemorySize, AT_SMEM);

  const int n4x = MTOT*HID/4;   // 2,097,152

  // 1) split x; transpose+split w_qkv
  k_split<<<(n4x + 255)/256, 256>>>((const float4*)x, n4x);
  k_splitT<<<dim3(QKVN/32, HID/32), 256>>>(w_qkv, QKVN);
  // 2) QKV GEMM (HMMA, 3-term) -> head-major bf16 hi/lo q/k/v (+bias fused)
  k_gemm<true><<<dim3(QKVN/128, MTOT/128), 256, G_SMEM>>>(b_qkv, nullptr, QKVN);
  // 3) HMMA flash attention -> ctx hi/lo straight into GEMM A buffers
  k_attn<<<dim3(SEQ/64, NH, BATCH), 128, AT_SMEM>>>();
  // 4) transpose+split w_o (reuses g_bhi/g_blo after QKV GEMM is done)
  k_splitT<<<dim3(HID/32, HID/32), 256>>>(w_o, HID);
  // 5) output projection -> d_out
  k_gemm<false><<<dim3(HID/128, MTOT/128), 256, G_SMEM>>>(nullptr, out, HID);
}

// round 9
// speedup vs baseline: 2.9584x; 1.0195x over previous
#include <cuda_runtime.h>
#include <cuda_bf16.h>
#include <cstdint>
#include <cstddef>

// Problem constants (fixed shapes).
#define BATCH 2
#define SEQ   2048
#define HID   2048
#define NH    16
#define HD    128
#define QKVN  (3*HID)   // 6144
#define MTOT  (BATCH*SEQ)

// Scratch (device globals; no allocations allowed).
__device__ __nv_bfloat16 g_ahi[(size_t)MTOT*HID];        // GEMM A hi (x, later ctx)
__device__ __nv_bfloat16 g_alo[(size_t)MTOT*HID];        // GEMM A lo
__device__ __nv_bfloat16 g_bhi[(size_t)QKVN*HID];        // weights^T hi [N][2048]
__device__ __nv_bfloat16 g_blo[(size_t)QKVN*HID];
__device__ __nv_bfloat16 g_qkvhi[(size_t)3*BATCH*NH*SEQ*HD];  // [which][b][h][s][d]
__device__ __nv_bfloat16 g_qkvlo[(size_t)3*BATCH*NH*SEQ*HD];

// ===========================================================================
// PTX helpers
// ===========================================================================
__device__ __forceinline__ unsigned smem_u32(const void* p) {
  unsigned a;
  asm("{ .reg .u64 t; cvta.to.shared.u64 t, %1; cvt.u32.u64 %0, t; }"
      : "=r"(a) : "l"(p));
  return a;
}
__device__ __forceinline__ void cp16(unsigned dst, const void* src) {
  asm volatile("cp.async.cg.shared.global [%0], [%1], 16;"
               :: "r"(dst), "l"(__cvta_generic_to_global(src)));
}
__device__ __forceinline__ void cp_commit() {
  asm volatile("cp.async.commit_group;" ::: "memory");
}
__device__ __forceinline__ void cp_wait1() {
  asm volatile("cp.async.wait_group 1;" ::: "memory");
}
__device__ __forceinline__ void ldsm4(unsigned* r, unsigned addr) {
  asm volatile("ldmatrix.sync.aligned.m8n8.x4.shared.b16 {%0,%1,%2,%3}, [%4];"
               : "=r"(r[0]), "=r"(r[1]), "=r"(r[2]), "=r"(r[3]) : "r"(addr));
}
__device__ __forceinline__ void ldsm4t(unsigned* r, unsigned addr) {
  asm volatile("ldmatrix.sync.aligned.m8n8.x4.trans.shared.b16 {%0,%1,%2,%3}, [%4];"
               : "=r"(r[0]), "=r"(r[1]), "=r"(r[2]), "=r"(r[3]) : "r"(addr));
}
__device__ __forceinline__ void mma_bf16(float* d, const unsigned* a,
                                         const unsigned* b) {
  asm volatile(
    "mma.sync.aligned.m16n8k16.row.col.f32.bf16.bf16.f32 "
    "{%0,%1,%2,%3}, {%4,%5,%6,%7}, {%8,%9}, {%0,%1,%2,%3};"
    : "+f"(d[0]), "+f"(d[1]), "+f"(d[2]), "+f"(d[3])
    : "r"(a[0]), "r"(a[1]), "r"(a[2]), "r"(a[3]), "r"(b[0]), "r"(b[1]));
}
__device__ __forceinline__ unsigned packbf(float lo, float hi) {
  unsigned r;
  asm("cvt.rn.bf16x2.f32 %0, %1, %2;" : "=r"(r) : "f"(hi), "f"(lo));
  return r;
}
__device__ __forceinline__ float blo(unsigned r) { return __int_as_float(r << 16); }
__device__ __forceinline__ float bhif(unsigned r) { return __int_as_float(r & 0xFFFF0000u); }

// ===========================================================================
// fp32 -> bf16 hi/lo split (elementwise) into g_ahi/g_alo
// ===========================================================================
__global__ void __launch_bounds__(256) k_split(const float4* __restrict__ in,
                                               int n4)
{
  int i = blockIdx.x * 256 + threadIdx.x;
  if (i >= n4) return;
  float4 v = in[i];
  __nv_bfloat16 h0 = __float2bfloat16(v.x), h1 = __float2bfloat16(v.y);
  __nv_bfloat16 h2 = __float2bfloat16(v.z), h3 = __float2bfloat16(v.w);
  __nv_bfloat16 l0 = __float2bfloat16(v.x - __bfloat162float(h0));
  __nv_bfloat16 l1 = __float2bfloat16(v.y - __bfloat162float(h1));
  __nv_bfloat16 l2 = __float2bfloat16(v.z - __bfloat162float(h2));
  __nv_bfloat16 l3 = __float2bfloat16(v.w - __bfloat162float(h3));
  __nv_bfloat162* hi = (__nv_bfloat162*)g_ahi;
  __nv_bfloat162* lo = (__nv_bfloat162*)g_alo;
  hi[2*i]   = __nv_bfloat162(h0, h1);
  hi[2*i+1] = __nv_bfloat162(h2, h3);
  lo[2*i]   = __nv_bfloat162(l0, l1);
  lo[2*i+1] = __nv_bfloat162(l2, l3);
}

// ===========================================================================
// w [K=2048][N] fp32 -> transposed hi/lo bf16 [N][2048] into g_bhi/g_blo
// ===========================================================================
__global__ void __launch_bounds__(256) k_splitT(const float* __restrict__ w,
                                                int N)
{
  __shared__ float t[32][33];
  const int n0 = blockIdx.x * 32, k0 = blockIdx.y * 32;
  const int tx = threadIdx.x & 31, ty = threadIdx.x >> 5;
#pragma unroll
  for (int i = 0; i < 4; ++i)
    t[ty + i*8][tx] = w[(size_t)(k0 + ty + i*8) * N + n0 + tx];
  __syncthreads();
#pragma unroll
  for (int i = 0; i < 4; ++i) {
    const int n = n0 + ty + i*8, k = k0 + tx;
    float v = t[tx][ty + i*8];
    __nv_bfloat16 h = __float2bfloat16(v);
    g_bhi[(size_t)n * HID + k] = h;
    g_blo[(size_t)n * HID + k] = __float2bfloat16(v - __bfloat162float(h));
  }
}

// ===========================================================================
// HMMA bf16 3-term split GEMM: C[M][N] = A[M][2048] @ B^T[N][2048]
// CTA tile 128x256, KC=32, 3-stage cp.async, 8 warps with 64x64 warp tiles.
// Smem stage: Ahi|Alo (128x40 each) | Bhi|Blo (256x40 each), 80B row stride.
// QKV=true: += bias, hi/lo split to g_qkvhi/lo in [which][b][h][s][d].
// ===========================================================================
#define KC 32
#define GST 3
#define A_MATB 10240u               // 128*80
#define B_MATB 20480u               // 256*80
#define STAGEB (2u*A_MATB + 2u*B_MATB)   // 61440
#define G_SMEM (GST*STAGEB)              // 184320

template<bool QKV>
__global__ void __launch_bounds__(256) k_gemm(const float* __restrict__ bias,
                                              float* __restrict__ Carg, int N)
{
  extern __shared__ __align__(128) char smem[];
  const unsigned sbase = smem_u32(smem);
  const int tid  = threadIdx.x;
  const int lane = tid & 31, wid = tid >> 5;
  const int m0 = blockIdx.y * 128, n0 = blockIdx.x * 256;
  const int K = HID;
  const int NC = K / KC;            // 64

  auto load_chunk = [&](int c) {
    const unsigned st = sbase + (unsigned)(c % GST) * STAGEB;
    const int koff = c * KC;
#pragma unroll
    for (int i = 0; i < 12; ++i) {
      const int q = tid + i * 256;     // 3072 16B segs
      unsigned dstoff; const __nv_bfloat16* src;
      if (q < 1024) {                  // A hi/lo: 128 rows x 4 segs each
        const int mat = q >> 9, idx = q & 511, row = idx >> 2, seg = idx & 3;
        dstoff = (unsigned)mat * A_MATB + (unsigned)row * 80u + (unsigned)seg * 16u;
        src = (mat ? g_alo : g_ahi) + (size_t)(m0 + row) * K + koff + seg * 8;
      } else {                         // B hi/lo: 256 rows x 4 segs each
        const int qq = q - 1024, mat = qq >> 10, idx = qq & 1023;
        const int row = idx >> 2, seg = idx & 3;
        dstoff = 2u*A_MATB + (unsigned)mat * B_MATB
               + (unsigned)row * 80u + (unsigned)seg * 16u;
        src = (mat ? g_blo : g_bhi) + (size_t)(n0 + row) * K + koff + seg * 8;
      }
      cp16(st + dstoff, src);
    }
  };

  // Warp tiling: wm in {0,1} -> 64 M rows; wn in [0,4) -> 64 N cols.
  const int wm = wid & 1, wn = wid >> 1;
  const unsigned aoff0 = (unsigned)(wm*64 + (lane & 15)) * 80u
                       + (unsigned)(lane >> 4) * 16u;
  const unsigned boff0 = 2u*A_MATB
                       + (unsigned)(wn*64 + (lane & 7) + ((lane >> 4) << 3)) * 80u
                       + (unsigned)((lane >> 3) & 1) * 16u;

  float acc[4][8][4];
#pragma unroll
  for (int mi = 0; mi < 4; ++mi)
#pragma unroll
    for (int nt = 0; nt < 8; ++nt)
#pragma unroll
      for (int r = 0; r < 4; ++r) acc[mi][nt][r] = 0.f;

  load_chunk(0); cp_commit();
  load_chunk(1); cp_commit();

  for (int c = 0; c < NC; ++c) {
    cp_wait1();                 // chunk c resident (c+1 may still be in flight)
    __syncthreads();            // all warps see it; slot (c+2)%3 reads all done
    if (c + 2 < NC) load_chunk(c + 2);
    cp_commit();

    const unsigned st = sbase + (unsigned)(c % GST) * STAGEB;
#pragma unroll
    for (int ks = 0; ks < 2; ++ks) {
      unsigned ah[4][4], al[4][4];
#pragma unroll
      for (int mi = 0; mi < 4; ++mi) {
        const unsigned a = st + aoff0 + (unsigned)mi*1280u + (unsigned)ks*32u;
        ldsm4(ah[mi], a);
        ldsm4(al[mi], a + A_MATB);
      }
#pragma unroll
      for (int nj = 0; nj < 4; ++nj) {
        unsigned bh[4], bl[4];
        const unsigned b = st + boff0 + (unsigned)nj*1280u + (unsigned)ks*32u;
        ldsm4(bh, b);
        ldsm4(bl, b + B_MATB);
#pragma unroll
        for (int mi = 0; mi < 4; ++mi)
#pragma unroll
          for (int hf = 0; hf < 2; ++hf) {
            float* a = acc[mi][nj*2 + hf];
            mma_bf16(a, ah[mi], &bh[hf*2]);
            mma_bf16(a, ah[mi], &bl[hf*2]);
            mma_bf16(a, al[mi], &bh[hf*2]);
          }
      }
    }
  }

  // Epilogue.
#pragma unroll
  for (int mi = 0; mi < 4; ++mi)
#pragma unroll
    for (int nt = 0; nt < 8; ++nt) {
      const int r0 = m0 + wm*64 + mi*16 + (lane >> 2);
      const int n  = n0 + wn*64 + nt*8 + (lane & 3)*2;
      if (QKV) {
        const float2 bv = *(const float2*)&bias[n];
        const float p0 = acc[mi][nt][0] + bv.x, p1 = acc[mi][nt][1] + bv.y;
        const float p2 = acc[mi][nt][2] + bv.x, p3 = acc[mi][nt][3] + bv.y;
        const int which = n >> 11, hh = (n >> 7) & 15, dd = n & 127;
        const int bb = r0 >> 11, s = r0 & 2047;
        const size_t o0 = ((size_t)((which*BATCH + bb)*NH + hh) * SEQ + s) * HD + dd;
        const size_t o1 = o0 + 8*HD;
        const unsigned h0 = packbf(p0, p1);
        const unsigned l0 = packbf(p0 - blo(h0), p1 - bhif(h0));
        const unsigned h1 = packbf(p2, p3);
        const unsigned l1 = packbf(p2 - blo(h1), p3 - bhif(h1));
        *(unsigned*)&g_qkvhi[o0] = h0;  *(unsigned*)&g_qkvlo[o0] = l0;
        *(unsigned*)&g_qkvhi[o1] = h1;  *(unsigned*)&g_qkvlo[o1] = l1;
      } else {
        *(float2*)&Carg[(size_t)r0 * N + n] =
            make_float2(acc[mi][nt][0], acc[mi][nt][1]);
        *(float2*)&Carg[(size_t)(r0 + 8) * N + n] =
            make_float2(acc[mi][nt][2], acc[mi][nt][3]);
      }
    }
}

// ===========================================================================
// HMMA flash attention (causal). 256 threads (8 warps), q-tile 128, k-tile 64.
// Q fragments hoisted to registers (staged through KV buffer 1), K/V double-
// buffered so cp.async overlaps compute. Warp w owns q rows [q0+16w, +16).
// S = qh*kh + qh*kl + ql*kh; PV = ph*vh + ph*vl + pl*vh (m16n8k16 bf16).
// ===========================================================================
#define AT_STR   272u                 // bytes per 128-col bf16 row (+pad)
#define AT_MATB  17408u               // 64*272   (one K or V matrix)
#define AT_KVST  (4u*AT_MATB)         // 69632    (Khi|Klo|Vhi|Vlo)
#define AT_SMEM  (2u*AT_KVST)         // 139264   (two stages)

__global__ void __launch_bounds__(256, 1) k_attn()
{
  extern __shared__ __align__(128) char smem[];
  const unsigned sb = smem_u32(smem);
  const int tid = threadIdx.x, lane = tid & 31, w = tid >> 5;
  const int qt = (int)gridDim.x - 1 - (int)blockIdx.x;   // heavy tiles first
  const int h = blockIdx.y, b = blockIdx.z;
  const int q0 = qt * 128;
  const int ktmax = 2*qt + 1;

  const size_t offQ = ((size_t)((0*BATCH + b)*NH + h)) * SEQ * HD;
  const size_t offK = ((size_t)((1*BATCH + b)*NH + h)) * SEQ * HD;
  const size_t offV = ((size_t)((2*BATCH + b)*NH + h)) * SEQ * HD;

  // Stage Q (hi+lo, 128 rows) into KV buffer 1 (freed before first use).
#pragma unroll
  for (int i = 0; i < 16; ++i) {
    const int q = tid + i * 256;              // 4096 segs
    const int mat = q >> 11, row = (q >> 4) & 127, seg = q & 15;
    cp16(sb + AT_KVST + (unsigned)mat * 34816u
            + (unsigned)row * AT_STR + (unsigned)seg * 16u,
         (mat ? g_qkvlo : g_qkvhi) + offQ + (size_t)(q0 + row) * HD + seg * 8);
  }
  cp_commit();

  auto stage_kv = [&](int kt) {
    const int k0 = kt * 64;
    const unsigned st = sb + (unsigned)(kt & 1) * AT_KVST;
#pragma unroll
    for (int i = 0; i < 16; ++i) {
      const int q = tid + i * 256;            // 4096 segs
      const int mat = q >> 10, row = (q >> 4) & 63, seg = q & 15;
      const __nv_bfloat16* base =
        (mat == 0) ? (g_qkvhi + offK) : (mat == 1) ? (g_qkvlo + offK)
      : (mat == 2) ? (g_qkvhi + offV) : (g_qkvlo + offV);
      cp16(st + (unsigned)mat * AT_MATB + (unsigned)row * AT_STR + (unsigned)seg * 16u,
           base + (size_t)(k0 + row) * HD + seg * 8);
    }
  };

  stage_kv(0); cp_commit();

  // ldmatrix per-lane offsets
  const unsigned aoff = (unsigned)(w*16 + (lane & 15)) * AT_STR
                      + (unsigned)(lane >> 4) * 16u;                 // Q rows
  const unsigned boff = (unsigned)((lane & 7) + ((lane >> 4) << 3)) * AT_STR
                      + (unsigned)((lane >> 3) & 1) * 16u;           // K cols
  const unsigned voff = (unsigned)(lane & 15) * AT_STR
                      + (unsigned)(lane >> 4) * 16u;                 // V (trans)

  // Hoist Q fragments into registers.
  unsigned qh[8][4], ql[8][4];
  cp_wait1();              // Q group done (KV0 may be in flight)
  __syncthreads();
#pragma unroll
  for (int kc = 0; kc < 8; ++kc) {
    ldsm4(qh[kc], sb + AT_KVST + aoff + (unsigned)kc*32u);
    ldsm4(ql[kc], sb + AT_KVST + 34816u + aoff + (unsigned)kc*32u);
  }
  __syncthreads();         // Q reads complete; buffer 1 free for KV(1)
  stage_kv(1); cp_commit();

  const float sc = 0.08838834764831845f;   // 1/sqrt(128)
  float m0r = -1e30f, m1r = -1e30f, l0 = 0.f, l1 = 0.f;
  float O[16][4];
#pragma unroll
  for (int nb = 0; nb < 16; ++nb)
#pragma unroll
    for (int r = 0; r < 4; ++r) O[nb][r] = 0.f;

  const int wrow = q0 + w*16;              // warp's first q row

  for (int kt = 0; kt <= ktmax; ++kt) {
    const int k0 = kt * 64;
    const unsigned st = sb + (unsigned)(kt & 1) * AT_KVST;
    cp_wait1();            // KV(kt) resident; KV(kt+1) still loading
    __syncthreads();

    if (k0 <= wrow + 15) {         // warp has at least one unmasked row
      // ---- S = Q K^T (3-term), 16x64 ----
      float S[8][4];
#pragma unroll
      for (int nb = 0; nb < 8; ++nb)
#pragma unroll
        for (int r = 0; r < 4; ++r) S[nb][r] = 0.f;

#pragma unroll
      for (int kc = 0; kc < 8; ++kc) {
#pragma unroll
        for (int j = 0; j < 4; ++j) {
          unsigned kh[4], kl[4];
          const unsigned bo = boff + (unsigned)j*4352u + (unsigned)kc*32u;
          ldsm4(kh, st + 0*AT_MATB + bo);
          ldsm4(kl, st + 1*AT_MATB + bo);
          mma_bf16(S[2*j],   qh[kc], &kh[0]);  mma_bf16(S[2*j+1], qh[kc], &kh[2]);
          mma_bf16(S[2*j],   qh[kc], &kl[0]);  mma_bf16(S[2*j+1], qh[kc], &kl[2]);
          mma_bf16(S[2*j],   ql[kc], &kh[0]);  mma_bf16(S[2*j+1], ql[kc], &kh[2]);
        }
      }

      // ---- causal mask (only near the diagonal) ----
      if (k0 + 63 > wrow) {
        const int rl0 = wrow + (lane >> 2), rl1 = rl0 + 8;
#pragma unroll
        for (int nb = 0; nb < 8; ++nb) {
          const int c0 = k0 + nb*8 + 2*(lane & 3), c1 = c0 + 1;
          if (c0 > rl0) S[nb][0] = -1e30f;
          if (c1 > rl0) S[nb][1] = -1e30f;
          if (c0 > rl1) S[nb][2] = -1e30f;
          if (c1 > rl1) S[nb][3] = -1e30f;
        }
      }

      // ---- online softmax ----
      float mx0 = -1e30f, mx1 = -1e30f;
#pragma unroll
      for (int nb = 0; nb < 8; ++nb) {
        mx0 = fmaxf(mx0, fmaxf(S[nb][0], S[nb][1]));
        mx1 = fmaxf(mx1, fmaxf(S[nb][2], S[nb][3]));
      }
      mx0 = fmaxf(mx0, __shfl_xor_sync(0xFFFFFFFFu, mx0, 1));
      mx0 = fmaxf(mx0, __shfl_xor_sync(0xFFFFFFFFu, mx0, 2));
      mx1 = fmaxf(mx1, __shfl_xor_sync(0xFFFFFFFFu, mx1, 1));
      mx1 = fmaxf(mx1, __shfl_xor_sync(0xFFFFFFFFu, mx1, 2));
      const float mn0 = fmaxf(m0r, mx0), mn1 = fmaxf(m1r, mx1);
      const float a0 = __expf(sc * (m0r - mn0));
      const float a1 = __expf(sc * (m1r - mn1));
      m0r = mn0; m1r = mn1;

      float ls0 = 0.f, ls1 = 0.f;
#pragma unroll
      for (int nb = 0; nb < 8; ++nb) {
        S[nb][0] = __expf(sc * (S[nb][0] - mn0));
        S[nb][1] = __expf(sc * (S[nb][1] - mn0));
        S[nb][2] = __expf(sc * (S[nb][2] - mn1));
        S[nb][3] = __expf(sc * (S[nb][3] - mn1));
        ls0 += S[nb][0] + S[nb][1];
        ls1 += S[nb][2] + S[nb][3];
      }
      l0 = l0 * a0 + ls0;
      l1 = l1 * a1 + ls1;

#pragma unroll
      for (int nb = 0; nb < 16; ++nb) {
        O[nb][0] *= a0; O[nb][1] *= a0;
        O[nb][2] *= a1; O[nb][3] *= a1;
      }

      // ---- P hi/lo fragments ----
      unsigned ph[4][4], pl[4][4];
#pragma unroll
      for (int kc2 = 0; kc2 < 4; ++kc2) {
        const float* p0 = S[2*kc2];
        const float* p1 = S[2*kc2+1];
        ph[kc2][0] = packbf(p0[0], p0[1]);
        ph[kc2][1] = packbf(p0[2], p0[3]);
        ph[kc2][2] = packbf(p1[0], p1[1]);
        ph[kc2][3] = packbf(p1[2], p1[3]);
        pl[kc2][0] = packbf(p0[0] - blo(ph[kc2][0]), p0[1] - bhif(ph[kc2][0]));
        pl[kc2][1] = packbf(p0[2] - blo(ph[kc2][1]), p0[3] - bhif(ph[kc2][1]));
        pl[kc2][2] = packbf(p1[0] - blo(ph[kc2][2]), p1[1] - bhif(ph[kc2][2]));
        pl[kc2][3] = packbf(p1[2] - blo(ph[kc2][3]), p1[3] - bhif(ph[kc2][3]));
      }

      // ---- O += P V (3-term), 16x128 ----
#pragma unroll
      for (int kc2 = 0; kc2 < 4; ++kc2) {
#pragma unroll
        for (int j = 0; j < 8; ++j) {
          unsigned vh[4], vl[4];
          const unsigned vo = voff + (unsigned)kc2*4352u + (unsigned)j*32u;
          ldsm4t(vh, st + 2*AT_MATB + vo);
          ldsm4t(vl, st + 3*AT_MATB + vo);
          mma_bf16(O[2*j],   ph[kc2], &vh[0]);  mma_bf16(O[2*j+1], ph[kc2], &vh[2]);
          mma_bf16(O[2*j],   ph[kc2], &vl[0]);  mma_bf16(O[2*j+1], ph[kc2], &vl[2]);
          mma_bf16(O[2*j],   pl[kc2], &vh[0]);  mma_bf16(O[2*j+1], pl[kc2], &vh[2]);
        }
      }
    }

    __syncthreads();       // all warps done reading slot (kt&1)
    if (kt + 2 <= ktmax) stage_kv(kt + 2);
    cp_commit();
  }

  // ---- finalize ----
  l0 += __shfl_xor_sync(0xFFFFFFFFu, l0, 1);
  l0 += __shfl_xor_sync(0xFFFFFFFFu, l0, 2);
  l1 += __shfl_xor_sync(0xFFFFFFFFu, l1, 1);
  l1 += __shfl_xor_sync(0xFFFFFFFFu, l1, 2);
  const float inv0 = 1.f / l0, inv1 = 1.f / l1;

  const int s0 = q0 + w*16 + (lane >> 2), s1 = s0 + 8;
  const size_t rb0 = ((size_t)b*SEQ + s0) * HID + h*HD;
  const size_t rb1 = ((size_t)b*SEQ + s1) * HID + h*HD;
#pragma unroll
  for (int nb = 0; nb < 16; ++nb) {
    const int c = nb*8 + 2*(lane & 3);
    const float v0 = O[nb][0]*inv0, v1 = O[nb][1]*inv0;
    const float v2 = O[nb][2]*inv1, v3 = O[nb][3]*inv1;
    const unsigned h0 = packbf(v0, v1);
    const unsigned lo0 = packbf(v0 - blo(h0), v1 - bhif(h0));
    const unsigned h1 = packbf(v2, v3);
    const unsigned lo1 = packbf(v2 - blo(h1), v3 - bhif(h1));
    *(unsigned*)&g_ahi[rb0 + c] = h0;  *(unsigned*)&g_alo[rb0 + c] = lo0;
    *(unsigned*)&g_ahi[rb1 + c] = h1;  *(unsigned*)&g_alo[rb1 + c] = lo1;
  }
}

// ---------------------------------------------------------------------------
extern "C" void kernel_launch(void* const* d_in, const int* in_sizes, int n_in,
                              void* d_out, int out_size)
{
  const float* x     = (const float*)d_in[0];
  const float* w_qkv = (const float*)d_in[1];
  const float* b_qkv = (const float*)d_in[2];
  const float* w_o   = (const float*)d_in[3];
  float* out = (float*)d_out;

  cudaFuncSetAttribute(k_gemm<true>,  cudaFuncAttributeMaxDynamicSharedMemorySize, G_SMEM);
  cudaFuncSetAttribute(k_gemm<false>, cudaFuncAttributeMaxDynamicSharedMemorySize, G_SMEM);
  cudaFuncSetAttribute(k_attn, cudaFuncAttributeMaxDynamicSharedMemorySize, AT_SMEM);

  const int n4x = MTOT*HID/4;   // 2,097,152

  // 1) split x; transpose+split w_qkv
  k_split<<<(n4x + 255)/256, 256>>>((const float4*)x, n4x);
  k_splitT<<<dim3(QKVN/32, HID/32), 256>>>(w_qkv, QKVN);
  // 2) QKV GEMM (HMMA, 3-term) -> head-major bf16 hi/lo q/k/v (+bias fused)
  k_gemm<true><<<dim3(QKVN/256, MTOT/128), 256, G_SMEM>>>(b_qkv, nullptr, QKVN);
  // 3) HMMA flash attention -> ctx hi/lo straight into GEMM A buffers
  k_attn<<<dim3(SEQ/128, NH, BATCH), 256, AT_SMEM>>>();
  // 4) transpose+split w_o
  k_splitT<<<dim3(HID/32, HID/32), 256>>>(w_o, HID);
  // 5) output projection -> d_out
  k_gemm<false><<<dim3(HID/256, MTOT/128), 256, G_SMEM>>>(nullptr, out, HID);
}

// round 12
// speedup vs baseline: 3.2435x; 1.0964x over previous
#include <cuda_runtime.h>
#include <cuda_bf16.h>
#include <cstdint>
#include <cstddef>

// Problem constants (fixed shapes).
#define BATCH 2
#define SEQ   2048
#define HID   2048
#define NH    16
#define HD    128
#define QKVN  (3*HID)   // 6144
#define MTOT  (BATCH*SEQ)

// Scratch (device globals; no allocations allowed).
__device__ __nv_bfloat16 g_ahi[(size_t)MTOT*HID];        // GEMM A hi (x, later ctx)
__device__ __nv_bfloat16 g_alo[(size_t)MTOT*HID];        // GEMM A lo
__device__ __nv_bfloat16 g_bhi[(size_t)QKVN*HID];        // weights^T hi [N][2048]
__device__ __nv_bfloat16 g_blo[(size_t)QKVN*HID];
__device__ __nv_bfloat16 g_qkvhi[(size_t)3*BATCH*NH*SEQ*HD];  // [which][b][h][s][d]
__device__ __nv_bfloat16 g_qkvlo[(size_t)3*BATCH*NH*SEQ*HD];

// ===========================================================================
// PTX helpers
// ===========================================================================
__device__ __forceinline__ unsigned smem_u32(const void* p) {
  unsigned a;
  asm("{ .reg .u64 t; cvta.to.shared.u64 t, %1; cvt.u32.u64 %0, t; }"
      : "=r"(a) : "l"(p));
  return a;
}
__device__ __forceinline__ void cp16(unsigned dst, const void* src) {
  asm volatile("cp.async.cg.shared.global [%0], [%1], 16;"
               :: "r"(dst), "l"(__cvta_generic_to_global(src)));
}
__device__ __forceinline__ void cp_commit() {
  asm volatile("cp.async.commit_group;" ::: "memory");
}
__device__ __forceinline__ void cp_wait1() {
  asm volatile("cp.async.wait_group 1;" ::: "memory");
}
__device__ __forceinline__ void ldsm4(unsigned* r, unsigned addr) {
  asm volatile("ldmatrix.sync.aligned.m8n8.x4.shared.b16 {%0,%1,%2,%3}, [%4];"
               : "=r"(r[0]), "=r"(r[1]), "=r"(r[2]), "=r"(r[3]) : "r"(addr));
}
__device__ __forceinline__ void ldsm4t(unsigned* r, unsigned addr) {
  asm volatile("ldmatrix.sync.aligned.m8n8.x4.trans.shared.b16 {%0,%1,%2,%3}, [%4];"
               : "=r"(r[0]), "=r"(r[1]), "=r"(r[2]), "=r"(r[3]) : "r"(addr));
}
__device__ __forceinline__ void mma_bf16(float* d, const unsigned* a,
                                         const unsigned* b) {
  asm volatile(
    "mma.sync.aligned.m16n8k16.row.col.f32.bf16.bf16.f32 "
    "{%0,%1,%2,%3}, {%4,%5,%6,%7}, {%8,%9}, {%0,%1,%2,%3};"
    : "+f"(d[0]), "+f"(d[1]), "+f"(d[2]), "+f"(d[3])
    : "r"(a[0]), "r"(a[1]), "r"(a[2]), "r"(a[3]), "r"(b[0]), "r"(b[1]));
}
__device__ __forceinline__ unsigned packbf(float lo, float hi) {
  unsigned r;
  asm("cvt.rn.bf16x2.f32 %0, %1, %2;" : "=r"(r) : "f"(hi), "f"(lo));
  return r;
}
__device__ __forceinline__ float blo(unsigned r) { return __int_as_float(r << 16); }
__device__ __forceinline__ float bhif(unsigned r) { return __int_as_float(r & 0xFFFF0000u); }

// ===========================================================================
// fp32 -> bf16 hi/lo split (elementwise) into g_ahi/g_alo
// ===========================================================================
__global__ void __launch_bounds__(256) k_split(const float4* __restrict__ in,
                                               int n4)
{
  int i = blockIdx.x * 256 + threadIdx.x;
  if (i >= n4) return;
  float4 v = in[i];
  __nv_bfloat16 h0 = __float2bfloat16(v.x), h1 = __float2bfloat16(v.y);
  __nv_bfloat16 h2 = __float2bfloat16(v.z), h3 = __float2bfloat16(v.w);
  __nv_bfloat16 l0 = __float2bfloat16(v.x - __bfloat162float(h0));
  __nv_bfloat16 l1 = __float2bfloat16(v.y - __bfloat162float(h1));
  __nv_bfloat16 l2 = __float2bfloat16(v.z - __bfloat162float(h2));
  __nv_bfloat16 l3 = __float2bfloat16(v.w - __bfloat162float(h3));
  __nv_bfloat162* hi = (__nv_bfloat162*)g_ahi;
  __nv_bfloat162* lo = (__nv_bfloat162*)g_alo;
  hi[2*i]   = __nv_bfloat162(h0, h1);
  hi[2*i+1] = __nv_bfloat162(h2, h3);
  lo[2*i]   = __nv_bfloat162(l0, l1);
  lo[2*i+1] = __nv_bfloat162(l2, l3);
}

// ===========================================================================
// w [K=2048][N] fp32 -> transposed hi/lo bf16 [N][2048] into g_bhi/g_blo
// ===========================================================================
__global__ void __launch_bounds__(256) k_splitT(const float* __restrict__ w,
                                                int N)
{
  __shared__ float t[32][33];
  const int n0 = blockIdx.x * 32, k0 = blockIdx.y * 32;
  const int tx = threadIdx.x & 31, ty = threadIdx.x >> 5;
#pragma unroll
  for (int i = 0; i < 4; ++i)
    t[ty + i*8][tx] = w[(size_t)(k0 + ty + i*8) * N + n0 + tx];
  __syncthreads();
#pragma unroll
  for (int i = 0; i < 4; ++i) {
    const int n = n0 + ty + i*8, k = k0 + tx;
    float v = t[tx][ty + i*8];
    __nv_bfloat16 h = __float2bfloat16(v);
    g_bhi[(size_t)n * HID + k] = h;
    g_blo[(size_t)n * HID + k] = __float2bfloat16(v - __bfloat162float(h));
  }
}

// ===========================================================================
// HMMA bf16 3-term split GEMM: C[M][N] = A[M][2048] @ B^T[N][2048]
// CTA tile 128x128, KC=32, 2-stage cp.async, 8 warps (4M x 2N, 32x64 tiles).
// 80 KB smem + <=128 regs -> 2 CTAs/SM (4 warps/SMSP) for latency hiding.
// QKV=true: += bias, hi/lo split to g_qkvhi/lo in [which][b][h][s][d].
// ===========================================================================
#define KC 32
#define GST 2
#define MATB 10240u                 // 128*80 bytes (one matrix, pad-8 rows)
#define STAGEB (4u*MATB)            // 40960
#define G_SMEM (GST*STAGEB)         // 81920

template<bool QKV>
__global__ void __launch_bounds__(256, 2) k_gemm(const float* __restrict__ bias,
                                                 float* __restrict__ Carg, int N)
{
  extern __shared__ __align__(128) char smem[];
  const unsigned sbase = smem_u32(smem);
  const int tid  = threadIdx.x;
  const int lane = tid & 31, wid = tid >> 5;
  const int m0 = blockIdx.y * 128, n0 = blockIdx.x * 128;
  const int K = HID;
  const int NC = K / KC;            // 64

  auto load_chunk = [&](int c) {
    const unsigned st = sbase + (unsigned)(c & 1) * STAGEB;
    const int koff = c * KC;
#pragma unroll
    for (int i = 0; i < 8; ++i) {
      const int q   = tid + i * 256;   // 2048 16B segs
      const int mat = q >> 9, idx = q & 511, row = idx >> 2, seg = idx & 3;
      const __nv_bfloat16* base =
        (mat == 0) ? g_ahi : (mat == 1) ? g_alo : (mat == 2) ? g_bhi : g_blo;
      const int grow = ((mat < 2) ? m0 : n0) + row;
      cp16(sbase + (unsigned)(c & 1) * STAGEB + (unsigned)mat * MATB
               + (unsigned)row * 80u + (unsigned)seg * 16u,
           base + (size_t)grow * K + koff + seg * 8);
    }
    (void)st;
  };

  // Warp tiling: wm in [0,4) -> 32 M rows; wn in {0,1} -> 64 N cols.
  const int wm = wid & 3, wn = wid >> 2;
  const unsigned aoff0 = (unsigned)(wm*32 + (lane & 15)) * 80u
                       + (unsigned)(lane >> 4) * 16u;
  const unsigned boff0 = 2u*MATB
                       + (unsigned)(wn*64 + (lane & 7) + ((lane >> 4) << 3)) * 80u
                       + (unsigned)((lane >> 3) & 1) * 16u;

  float acc[2][8][4];
#pragma unroll
  for (int mi = 0; mi < 2; ++mi)
#pragma unroll
    for (int nt = 0; nt < 8; ++nt)
#pragma unroll
      for (int r = 0; r < 4; ++r) acc[mi][nt][r] = 0.f;

  load_chunk(0); cp_commit();

  for (int c = 0; c < NC; ++c) {
    if (c + 1 < NC) load_chunk(c + 1);
    cp_commit();                // empty group at the tail keeps counts aligned
    cp_wait1();                 // chunk c resident (c+1 still in flight)
    __syncthreads();            // visible to all warps

    const unsigned st = sbase + (unsigned)(c & 1) * STAGEB;
#pragma unroll
    for (int ks = 0; ks < 2; ++ks) {
      unsigned ah[2][4], al[2][4];
#pragma unroll
      for (int mi = 0; mi < 2; ++mi) {
        const unsigned a = st + aoff0 + (unsigned)mi*1280u + (unsigned)ks*32u;
        ldsm4(ah[mi], a);
        ldsm4(al[mi], a + MATB);
      }
#pragma unroll
      for (int nj = 0; nj < 4; ++nj) {
        unsigned bh[4], bl[4];
        const unsigned b = st + boff0 + (unsigned)nj*1280u + (unsigned)ks*32u;
        ldsm4(bh, b);
        ldsm4(bl, b + MATB);
#pragma unroll
        for (int mi = 0; mi < 2; ++mi)
#pragma unroll
          for (int hf = 0; hf < 2; ++hf) {
            float* a = acc[mi][nj*2 + hf];
            mma_bf16(a, ah[mi], &bh[hf*2]);
            mma_bf16(a, ah[mi], &bl[hf*2]);
            mma_bf16(a, al[mi], &bh[hf*2]);
          }
      }
    }
    __syncthreads();            // reads of slot (c&1) done before load(c+2)
  }

  // Epilogue.
#pragma unroll
  for (int mi = 0; mi < 2; ++mi)
#pragma unroll
    for (int nt = 0; nt < 8; ++nt) {
      const int r0 = m0 + wm*32 + mi*16 + (lane >> 2);
      const int n  = n0 + wn*64 + nt*8 + (lane & 3)*2;
      if (QKV) {
        const float2 bv = *(const float2*)&bias[n];
        const float p0 = acc[mi][nt][0] + bv.x, p1 = acc[mi][nt][1] + bv.y;
        const float p2 = acc[mi][nt][2] + bv.x, p3 = acc[mi][nt][3] + bv.y;
        const int which = n >> 11, hh = (n >> 7) & 15, dd = n & 127;
        const int bb = r0 >> 11, s = r0 & 2047;
        const size_t o0 = ((size_t)((which*BATCH + bb)*NH + hh) * SEQ + s) * HD + dd;
        const size_t o1 = o0 + 8*HD;
        const unsigned h0 = packbf(p0, p1);
        const unsigned l0 = packbf(p0 - blo(h0), p1 - bhif(h0));
        const unsigned h1 = packbf(p2, p3);
        const unsigned l1 = packbf(p2 - blo(h1), p3 - bhif(h1));
        *(unsigned*)&g_qkvhi[o0] = h0;  *(unsigned*)&g_qkvlo[o0] = l0;
        *(unsigned*)&g_qkvhi[o1] = h1;  *(unsigned*)&g_qkvlo[o1] = l1;
      } else {
        *(float2*)&Carg[(size_t)r0 * N + n] =
            make_float2(acc[mi][nt][0], acc[mi][nt][1]);
        *(float2*)&Carg[(size_t)(r0 + 8) * N + n] =
            make_float2(acc[mi][nt][2], acc[mi][nt][3]);
      }
    }
}

// ===========================================================================
// HMMA flash attention (causal). 256 threads (8 warps), q-tile 128, k-tile 64.
// Q-hi fragments in registers; Q-lo stays in a dedicated smem block (one extra
// ldsm per k-chunk) to avoid register spills. K/V double-buffered (wait_group 1)
// so cp.async overlaps compute. Warp w owns q rows [q0+16w, +16).
// S = qh*kh + qh*kl + ql*kh; PV = ph*vh + ph*vl + pl*vh (m16n8k16 bf16).
// ===========================================================================
#define AT_STR   272u                 // bytes per 128-col bf16 row (+pad)
#define AT_MATB  17408u               // 64*272   (one K or V matrix)
#define AT_KVST  (4u*AT_MATB)         // 69632    (Khi|Klo|Vhi|Vlo)
#define AT_QLO   (2u*AT_KVST)         // 139264   (Q-lo block, 128 rows)
#define AT_SMEM  (AT_QLO + 34816u)    // 174080

__global__ void __launch_bounds__(256, 1) k_attn()
{
  extern __shared__ __align__(128) char smem[];
  const unsigned sb = smem_u32(smem);
  const int tid = threadIdx.x, lane = tid & 31, w = tid >> 5;
  const int qt = (int)gridDim.x - 1 - (int)blockIdx.x;   // heavy tiles first
  const int h = blockIdx.y, b = blockIdx.z;
  const int q0 = qt * 128;
  const int ktmax = 2*qt + 1;

  const size_t offQ = ((size_t)((0*BATCH + b)*NH + h)) * SEQ * HD;
  const size_t offK = ((size_t)((1*BATCH + b)*NH + h)) * SEQ * HD;
  const size_t offV = ((size_t)((2*BATCH + b)*NH + h)) * SEQ * HD;

  // Stage Q: hi -> KV buffer 1 (transient; consumed into regs), lo -> AT_QLO.
#pragma unroll
  for (int i = 0; i < 16; ++i) {
    const int q = tid + i * 256;              // 4096 segs
    const int mat = q >> 11, row = (q >> 4) & 127, seg = q & 15;
    const unsigned dst = (mat ? (sb + AT_QLO) : (sb + AT_KVST))
                       + (unsigned)row * AT_STR + (unsigned)seg * 16u;
    cp16(dst, (mat ? g_qkvlo : g_qkvhi) + offQ + (size_t)(q0 + row) * HD + seg * 8);
  }
  cp_commit();

  auto stage_kv = [&](int kt) {
    const int k0 = kt * 64;
    const unsigned st = sb + (unsigned)(kt & 1) * AT_KVST;
#pragma unroll
    for (int i = 0; i < 16; ++i) {
      const int q = tid + i * 256;            // 4096 segs
      const int mat = q >> 10, row = (q >> 4) & 63, seg = q & 15;
      const __nv_bfloat16* base =
        (mat == 0) ? (g_qkvhi + offK) : (mat == 1) ? (g_qkvlo + offK)
      : (mat == 2) ? (g_qkvhi + offV) : (g_qkvlo + offV);
      cp16(st + (unsigned)mat * AT_MATB + (unsigned)row * AT_STR + (unsigned)seg * 16u,
           base + (size_t)(k0 + row) * HD + seg * 8);
    }
  };

  stage_kv(0); cp_commit();

  // ldmatrix per-lane offsets
  const unsigned aoff = (unsigned)(w*16 + (lane & 15)) * AT_STR
                      + (unsigned)(lane >> 4) * 16u;                 // Q rows
  const unsigned boff = (unsigned)((lane & 7) + ((lane >> 4) << 3)) * AT_STR
                      + (unsigned)((lane >> 3) & 1) * 16u;           // K cols
  const unsigned voff = (unsigned)(lane & 15) * AT_STR
                      + (unsigned)(lane >> 4) * 16u;                 // V (trans)

  // Hoist Q-hi fragments into registers (Q-lo stays in smem).
  unsigned qh[8][4];
  cp_wait1();              // Q group done (KV0 may be in flight)
  __syncthreads();
#pragma unroll
  for (int kc = 0; kc < 8; ++kc)
    ldsm4(qh[kc], sb + AT_KVST + aoff + (unsigned)kc*32u);
  __syncthreads();         // Q-hi reads complete; buffer 1 free for KV(1)
  stage_kv(1); cp_commit();

  const float sc = 0.08838834764831845f;   // 1/sqrt(128)
  float m0r = -1e30f, m1r = -1e30f, l0 = 0.f, l1 = 0.f;
  float O[16][4];
#pragma unroll
  for (int nb = 0; nb < 16; ++nb)
#pragma unroll
    for (int r = 0; r < 4; ++r) O[nb][r] = 0.f;

  const int wrow = q0 + w*16;              // warp's first q row

  for (int kt = 0; kt <= ktmax; ++kt) {
    const int k0 = kt * 64;
    const unsigned st = sb + (unsigned)(kt & 1) * AT_KVST;
    cp_wait1();            // KV(kt) resident; KV(kt+1) still loading
    __syncthreads();

    if (k0 <= wrow + 15) {         // warp has at least one unmasked row
      // ---- S = Q K^T (3-term), 16x64 ----
      float S[8][4];
#pragma unroll
      for (int nb = 0; nb < 8; ++nb)
#pragma unroll
        for (int r = 0; r < 4; ++r) S[nb][r] = 0.f;

#pragma unroll
      for (int kc = 0; kc < 8; ++kc) {
        unsigned qlr[4];
        ldsm4(qlr, sb + AT_QLO + aoff + (unsigned)kc*32u);
#pragma unroll
        for (int j = 0; j < 4; ++j) {
          unsigned kh[4], kl[4];
          const unsigned bo = boff + (unsigned)j*4352u + (unsigned)kc*32u;
          ldsm4(kh, st + 0*AT_MATB + bo);
          ldsm4(kl, st + 1*AT_MATB + bo);
          mma_bf16(S[2*j],   qh[kc], &kh[0]);  mma_bf16(S[2*j+1], qh[kc], &kh[2]);
          mma_bf16(S[2*j],   qh[kc], &kl[0]);  mma_bf16(S[2*j+1], qh[kc], &kl[2]);
          mma_bf16(S[2*j],   qlr,    &kh[0]);  mma_bf16(S[2*j+1], qlr,    &kh[2]);
        }
      }

      // ---- causal mask (only near the diagonal) ----
      if (k0 + 63 > wrow) {
        const int rl0 = wrow + (lane >> 2), rl1 = rl0 + 8;
#pragma unroll
        for (int nb = 0; nb < 8; ++nb) {
          const int c0 = k0 + nb*8 + 2*(lane & 3), c1 = c0 + 1;
          if (c0 > rl0) S[nb][0] = -1e30f;
          if (c1 > rl0) S[nb][1] = -1e30f;
          if (c0 > rl1) S[nb][2] = -1e30f;
          if (c1 > rl1) S[nb][3] = -1e30f;
        }
      }

      // ---- online softmax ----
      float mx0 = -1e30f, mx1 = -1e30f;
#pragma unroll
      for (int nb = 0; nb < 8; ++nb) {
        mx0 = fmaxf(mx0, fmaxf(S[nb][0], S[nb][1]));
        mx1 = fmaxf(mx1, fmaxf(S[nb][2], S[nb][3]));
      }
      mx0 = fmaxf(mx0, __shfl_xor_sync(0xFFFFFFFFu, mx0, 1));
      mx0 = fmaxf(mx0, __shfl_xor_sync(0xFFFFFFFFu, mx0, 2));
      mx1 = fmaxf(mx1, __shfl_xor_sync(0xFFFFFFFFu, mx1, 1));
      mx1 = fmaxf(mx1, __shfl_xor_sync(0xFFFFFFFFu, mx1, 2));
      const float mn0 = fmaxf(m0r, mx0), mn1 = fmaxf(m1r, mx1);
      const float a0 = __expf(sc * (m0r - mn0));
      const float a1 = __expf(sc * (m1r - mn1));
      m0r = mn0; m1r = mn1;

      float ls0 = 0.f, ls1 = 0.f;
#pragma unroll
      for (int nb = 0; nb < 8; ++nb) {
        S[nb][0] = __expf(sc * (S[nb][0] - mn0));
        S[nb][1] = __expf(sc * (S[nb][1] - mn0));
        S[nb][2] = __expf(sc * (S[nb][2] - mn1));
        S[nb][3] = __expf(sc * (S[nb][3] - mn1));
        ls0 += S[nb][0] + S[nb][1];
        ls1 += S[nb][2] + S[nb][3];
      }
      l0 = l0 * a0 + ls0;
      l1 = l1 * a1 + ls1;

#pragma unroll
      for (int nb = 0; nb < 16; ++nb) {
        O[nb][0] *= a0; O[nb][1] *= a0;
        O[nb][2] *= a1; O[nb][3] *= a1;
      }

      // ---- P hi/lo fragments ----
      unsigned ph[4][4], pl[4][4];
#pragma unroll
      for (int kc2 = 0; kc2 < 4; ++kc2) {
        const float* p0 = S[2*kc2];
        const float* p1 = S[2*kc2+1];
        ph[kc2][0] = packbf(p0[0], p0[1]);
        ph[kc2][1] = packbf(p0[2], p0[3]);
        ph[kc2][2] = packbf(p1[0], p1[1]);
        ph[kc2][3] = packbf(p1[2], p1[3]);
        pl[kc2][0] = packbf(p0[0] - blo(ph[kc2][0]), p0[1] - bhif(ph[kc2][0]));
        pl[kc2][1] = packbf(p0[2] - blo(ph[kc2][1]), p0[3] - bhif(ph[kc2][1]));
        pl[kc2][2] = packbf(p1[0] - blo(ph[kc2][2]), p1[1] - bhif(ph[kc2][2]));
        pl[kc2][3] = packbf(p1[2] - blo(ph[kc2][3]), p1[3] - bhif(ph[kc2][3]));
      }

      // ---- O += P V (3-term), 16x128 ----
#pragma unroll
      for (int kc2 = 0; kc2 < 4; ++kc2) {
#pragma unroll
        for (int j = 0; j < 8; ++j) {
          unsigned vh[4], vl[4];
          const unsigned vo = voff + (unsigned)kc2*4352u + (unsigned)j*32u;
          ldsm4t(vh, st + 2*AT_MATB + vo);
          ldsm4t(vl, st + 3*AT_MATB + vo);
          mma_bf16(O[2*j],   ph[kc2], &vh[0]);  mma_bf16(O[2*j+1], ph[kc2], &vh[2]);
          mma_bf16(O[2*j],   ph[kc2], &vl[0]);  mma_bf16(O[2*j+1], ph[kc2], &vl[2]);
          mma_bf16(O[2*j],   pl[kc2], &vh[0]);  mma_bf16(O[2*j+1], pl[kc2], &vh[2]);
        }
      }
    }

    __syncthreads();       // all warps done reading slot (kt&1)
    if (kt + 2 <= ktmax) stage_kv(kt + 2);
    cp_commit();
  }

  // ---- finalize ----
  l0 += __shfl_xor_sync(0xFFFFFFFFu, l0, 1);
  l0 += __shfl_xor_sync(0xFFFFFFFFu, l0, 2);
  l1 += __shfl_xor_sync(0xFFFFFFFFu, l1, 1);
  l1 += __shfl_xor_sync(0xFFFFFFFFu, l1, 2);
  const float inv0 = 1.f / l0, inv1 = 1.f / l1;

  const int s0 = q0 + w*16 + (lane >> 2), s1 = s0 + 8;
  const size_t rb0 = ((size_t)b*SEQ + s0) * HID + h*HD;
  const size_t rb1 = ((size_t)b*SEQ + s1) * HID + h*HD;
#pragma unroll
  for (int nb = 0; nb < 16; ++nb) {
    const int c = nb*8 + 2*(lane & 3);
    const float v0 = O[nb][0]*inv0, v1 = O[nb][1]*inv0;
    const float v2 = O[nb][2]*inv1, v3 = O[nb][3]*inv1;
    const unsigned h0 = packbf(v0, v1);
    const unsigned lo0 = packbf(v0 - blo(h0), v1 - bhif(h0));
    const unsigned h1 = packbf(v2, v3);
    const unsigned lo1 = packbf(v2 - blo(h1), v3 - bhif(h1));
    *(unsigned*)&g_ahi[rb0 + c] = h0;  *(unsigned*)&g_alo[rb0 + c] = lo0;
    *(unsigned*)&g_ahi[rb1 + c] = h1;  *(unsigned*)&g_alo[rb1 + c] = lo1;
  }
}

// ---------------------------------------------------------------------------
extern "C" void kernel_launch(void* const* d_in, const int* in_sizes, int n_in,
                              void* d_out, int out_size)
{
  const float* x     = (const float*)d_in[0];
  const float* w_qkv = (const float*)d_in[1];
  const float* b_qkv = (const float*)d_in[2];
  const float* w_o   = (const float*)d_in[3];
  float* out = (float*)d_out;

  cudaFuncSetAttribute(k_gemm<true>,  cudaFuncAttributeMaxDynamicSharedMemorySize, G_SMEM);
  cudaFuncSetAttribute(k_gemm<false>, cudaFuncAttributeMaxDynamicSharedMemorySize, G_SMEM);
  cudaFuncSetAttribute(k_attn, cudaFuncAttributeMaxDynamicSharedMemorySize, AT_SMEM);

  const int n4x = MTOT*HID/4;   // 2,097,152

  // 1) split x; transpose+split w_qkv
  k_split<<<(n4x + 255)/256, 256>>>((const float4*)x, n4x);
  k_splitT<<<dim3(QKVN/32, HID/32), 256>>>(w_qkv, QKVN);
  // 2) QKV GEMM (HMMA, 3-term) -> head-major bf16 hi/lo q/k/v (+bias fused)
  k_gemm<true><<<dim3(QKVN/128, MTOT/128), 256, G_SMEM>>>(b_qkv, nullptr, QKVN);
  // 3) HMMA flash attention -> ctx hi/lo straight into GEMM A buffers
  k_attn<<<dim3(SEQ/128, NH, BATCH), 256, AT_SMEM>>>();
  // 4) transpose+split w_o
  k_splitT<<<dim3(HID/32, HID/32), 256>>>(w_o, HID);
  // 5) output projection -> d_out
  k_gemm<false><<<dim3(HID/128, MTOT/128), 256, G_SMEM>>>(nullptr, out, HID);
}